// round 9
// baseline (speedup 1.0000x reference)
#include <cuda_runtime.h>
#include <cuda_fp16.h>
#include <cstdint>

#define NN 50000
#define EE 800000
#define RR 6
#define FF 128
#define SEG (RR * NN)
#define NCHUNK 4
#define CHN 12544                      // chunk node count (multiple of 64)

// ---------------- scratch (static device globals; no allocations) ----------------
__device__ __align__(16) __half g_nodeH[(size_t)NN * FF];  // 12.8 MB fp16 node_h
__device__ __align__(16) __half g_aggH[(size_t)SEG * FF];  // 76.8 MB fp16 agg
__device__ __align__(16) float g_c1[NN * RR];
__device__ __align__(16) float g_c2[NN * RR];
__device__ __align__(16) float g_v1[RR * FF];
__device__ __align__(16) float g_v2[RR * FF];
__device__ __align__(16) __half g_Wh[RR * FF * FF];        // [r][o][f] = W[r][f][o] fp16
__device__ __align__(16) __half g_Wc1h[FF * FF];           // [o][k] fp16
__device__ __align__(16) __half g_Wc2h[FF * FF];
__device__ __align__(16) float g_e1[SEG];
__device__ __align__(16) float g_e2[SEG];
__device__ __align__(16) int g_cnt[SEG];
__device__ __align__(16) int g_off[SEG];
__device__ __align__(16) int g_cur[SEG];
__device__ __align__(16) int g_bsum[1024];
__device__ __align__(16) int g_src_sorted[EE];

__device__ __forceinline__ void cpa16(void* dst_smem, const void* src) {
    uint32_t d = (uint32_t)__cvta_generic_to_shared(dst_smem);
    asm volatile("cp.async.cg.shared.global [%0], [%1], 16;" :: "r"(d), "l"(src));
}

// ---------------- K0: precompute v1,v2 and fp16 W^T per relation ----------------
__global__ void precompute_kernel(const float* __restrict__ W,
                                  const float* __restrict__ att1,
                                  const float* __restrict__ att2) {
    __shared__ float red1[128];
    __shared__ float red2[128];
    int rf = blockIdx.x;           // r*128 + f
    int r  = rf >> 7, f = rf & 127;
    int o  = threadIdx.x;
    float w = W[rf * 128 + o];
    g_Wh[(size_t)r * (FF * FF) + o * FF + f] = __float2half_rn(w);

    red1[o] = w * att1[o];
    red2[o] = w * att2[o];
    __syncthreads();
    for (int s = 64; s > 0; s >>= 1) {
        if (o < s) { red1[o] += red1[o + s]; red2[o] += red2[o + s]; }
        __syncthreads();
    }
    if (o == 0) { g_v1[rf] = red1[0]; g_v2[rf] = red2[0]; }
}

__global__ void wc_convert_kernel(const float* __restrict__ Wc) {
    int o = blockIdx.x, k = threadIdx.x;
    g_Wc1h[o * FF + k] = __float2half_rn(Wc[o * 256 + k]);
    g_Wc2h[o * FF + k] = __float2half_rn(Wc[o * 256 + 128 + k]);
}

// ---------------- convert node_h -> fp16 ----------------
__global__ void nodeh_convert_kernel(const float* __restrict__ node_h) {
    size_t i = (size_t)blockIdx.x * blockDim.x + threadIdx.x;   // one per 8 elems
    if (i >= (size_t)NN * FF / 8) return;
    const float4* p = reinterpret_cast<const float4*>(node_h) + i * 2;
    float4 a = p[0], b = p[1];
    __half2 h0 = __floats2half2_rn(a.x, a.y);
    __half2 h1 = __floats2half2_rn(a.z, a.w);
    __half2 h2 = __floats2half2_rn(b.x, b.y);
    __half2 h3 = __floats2half2_rn(b.z, b.w);
    uint4 o;
    o.x = *reinterpret_cast<uint32_t*>(&h0);
    o.y = *reinterpret_cast<uint32_t*>(&h1);
    o.z = *reinterpret_cast<uint32_t*>(&h2);
    o.w = *reinterpret_cast<uint32_t*>(&h3);
    reinterpret_cast<uint4*>(g_nodeH)[i] = o;
}

// ---------------- CSR build ----------------
__global__ void zero_cnt_kernel() {
    int i = blockIdx.x * blockDim.x + threadIdx.x;
    if (i < SEG) g_cnt[i] = 0;
}
__global__ void hist_kernel(const int* __restrict__ edst, const int* __restrict__ erel) {
    int i = blockIdx.x * blockDim.x + threadIdx.x;
    if (i >= EE) return;
    atomicAdd(&g_cnt[erel[i] * NN + edst[i]], 1);
}
__global__ void scan1_kernel() {
    __shared__ int sm[512];
    int tid = threadIdx.x;
    int idx = blockIdx.x * 512 + tid;
    int v = (idx < SEG) ? g_cnt[idx] : 0;
    sm[tid] = v;
    __syncthreads();
#pragma unroll
    for (int s = 1; s < 512; s <<= 1) {
        int add = (tid >= s) ? sm[tid - s] : 0;
        __syncthreads();
        sm[tid] += add;
        __syncthreads();
    }
    int incl = sm[tid];
    if (idx < SEG) g_off[idx] = incl - v;
    if (tid == 511) g_bsum[blockIdx.x] = incl;
}
__global__ void scan2_kernel(int nblk) {
    __shared__ int sm[1024];
    int tid = threadIdx.x;
    int v = (tid < nblk) ? g_bsum[tid] : 0;
    sm[tid] = v;
    __syncthreads();
#pragma unroll
    for (int s = 1; s < 1024; s <<= 1) {
        int add = (tid >= s) ? sm[tid - s] : 0;
        __syncthreads();
        sm[tid] += add;
        __syncthreads();
    }
    if (tid < nblk) g_bsum[tid] = sm[tid] - v;
}
__global__ void scan3_kernel() {
    int idx = blockIdx.x * blockDim.x + threadIdx.x;
    if (idx >= SEG) return;
    int o = g_off[idx] + g_bsum[idx >> 9];
    g_off[idx] = o;
    g_cur[idx] = o;
}
__global__ void permute_kernel(const int* __restrict__ esrc,
                               const int* __restrict__ edst,
                               const int* __restrict__ erel) {
    int i = blockIdx.x * blockDim.x + threadIdx.x;
    if (i >= EE) return;
    int key = erel[i] * NN + edst[i];
    int pos = atomicAdd(&g_cur[key], 1);
    g_src_sorted[pos] = esrc[i];
}

// ---------------- gather (chunked): one warp per (rel,dst) segment ----------------
__global__ __launch_bounds__(256) void gather_kernel(int n0, int cnt) {
    int w = blockIdx.x * 8 + (threadIdx.x >> 5);
    if (w >= RR * cnt) return;
    int l = threadIdx.x & 31;
    int r = w / cnt;
    int n = n0 + (w - r * cnt);
    int seg = r * NN + n;
    int off = g_off[seg];
    int deg = g_cnt[seg];

    const uint2* h2 = reinterpret_cast<const uint2*>(g_nodeH);
    float4 acc = make_float4(0.f, 0.f, 0.f, 0.f);
    int e = 0;
    for (; e + 2 <= deg; e += 2) {
        int i0 = g_src_sorted[off + e];
        int i1 = g_src_sorted[off + e + 1];
        uint2 ua = h2[(size_t)i0 * 32 + l];
        uint2 ub = h2[(size_t)i1 * 32 + l];
        float2 a0 = __half22float2(*reinterpret_cast<__half2*>(&ua.x));
        float2 a1 = __half22float2(*reinterpret_cast<__half2*>(&ua.y));
        float2 b0 = __half22float2(*reinterpret_cast<__half2*>(&ub.x));
        float2 b1 = __half22float2(*reinterpret_cast<__half2*>(&ub.y));
        acc.x += a0.x + b0.x; acc.y += a0.y + b0.y;
        acc.z += a1.x + b1.x; acc.w += a1.y + b1.y;
    }
    if (e < deg) {
        int i0 = g_src_sorted[off + e];
        uint2 ua = h2[(size_t)i0 * 32 + l];
        float2 a0 = __half22float2(*reinterpret_cast<__half2*>(&ua.x));
        float2 a1 = __half22float2(*reinterpret_cast<__half2*>(&ua.y));
        acc.x += a0.x; acc.y += a0.y; acc.z += a1.x; acc.w += a1.y;
    }

    __half2 h01 = __floats2half2_rn(acc.x, acc.y);
    __half2 h23 = __floats2half2_rn(acc.z, acc.w);
    uint2 packed;
    packed.x = *reinterpret_cast<uint32_t*>(&h01);
    packed.y = *reinterpret_cast<uint32_t*>(&h23);
    reinterpret_cast<uint2*>(g_aggH)[(size_t)seg * 32 + l] = packed;

    float4 w1 = reinterpret_cast<const float4*>(g_v1)[r * 32 + l];
    float4 w2 = reinterpret_cast<const float4*>(g_v2)[r * 32 + l];
    float p1 = acc.x * w1.x + acc.y * w1.y + acc.z * w1.z + acc.w * w1.w;
    float p2 = acc.x * w2.x + acc.y * w2.y + acc.z * w2.z + acc.w * w2.w;
#pragma unroll
    for (int s = 16; s > 0; s >>= 1) {
        p1 += __shfl_xor_sync(0xffffffffu, p1, s);
        p2 += __shfl_xor_sync(0xffffffffu, p2, s);
    }
    if (l == 0) { g_e1[seg] = p1; g_e2[seg] = p2; }
}

// ---------------- per-node softmax (chunked) ----------------
__global__ void softmax_kernel(int n0, int cnt) {
    int i = blockIdx.x * blockDim.x + threadIdx.x;
    if (i >= cnt) return;
    int n = n0 + i;
    float e1[RR], e2[RR], dg[RR];
#pragma unroll
    for (int r = 0; r < RR; r++) {
        dg[r] = 1.0f + (float)g_cnt[r * NN + n];
        e1[r] = g_e1[r * NN + n] / dg[r];
        e2[r] = g_e2[r * NN + n] / dg[r];
    }
    float m1 = e1[0], m2 = e2[0];
#pragma unroll
    for (int r = 1; r < RR; r++) { m1 = fmaxf(m1, e1[r]); m2 = fmaxf(m2, e2[r]); }
    float s1 = 0.f, s2 = 0.f;
#pragma unroll
    for (int r = 0; r < RR; r++) {
        e1[r] = __expf(e1[r] - m1); s1 += e1[r];
        e2[r] = __expf(e2[r] - m2); s2 += e2[r];
    }
    float i1 = 1.0f / s1, i2 = 1.0f / s2;
#pragma unroll
    for (int r = 0; r < RR; r++) {
        g_c1[n * RR + r] = e1[r] * i1 / dg[r];
        g_c2[n * RR + r] = e2[r] * i2 / dg[r];
    }
}

// ---------------- K4: fused factored GEMM (chunked) ----------------
__device__ __forceinline__ void mma16(float d[4], uint32_t a0, uint32_t a1, uint32_t a2, uint32_t a3,
                                      uint32_t b0, uint32_t b1) {
    asm volatile(
        "mma.sync.aligned.m16n8k16.row.col.f32.f16.f16.f32 "
        "{%0,%1,%2,%3},{%4,%5,%6,%7},{%8,%9},{%0,%1,%2,%3};"
        : "+f"(d[0]), "+f"(d[1]), "+f"(d[2]), "+f"(d[3])
        : "r"(a0), "r"(a1), "r"(a2), "r"(a3), "r"(b0), "r"(b1));
}

#define STR 136
#define AH_OFF 0
#define BW_OFF (2 * 64 * STR)
#define YZ_OFF (BW_OFF + 2 * 128 * STR)
#define WC2_OFF (YZ_OFF + 2 * 64 * STR)
#define GEMM_SMEM ((WC2_OFF + 128 * STR) * 2)   // 174080 bytes

__global__ __launch_bounds__(256, 1) void gemm_kernel(float* __restrict__ out,
                                                      const float* __restrict__ bc,
                                                      int nbase) {
    extern __shared__ __half sh[];
    __half* Ah   = sh + AH_OFF;
    __half* Bw   = sh + BW_OFF;
    __half* Yz   = sh + YZ_OFF;
    __half* Wc2s = sh + WC2_OFF;

    int n0 = nbase + blockIdx.x * 64;
    int t = threadIdx.x;
    int warp = t >> 5, lane = t & 31;
    int wm = warp >> 2, wn = warp & 3;
    int g = lane >> 2, tg = lane & 3;

    float P[2][4][4], Y[2][4][4], Z[2][4][4];
#pragma unroll
    for (int mi = 0; mi < 2; mi++)
#pragma unroll
        for (int ni = 0; ni < 4; ni++)
#pragma unroll
            for (int j = 0; j < 4; j++) { P[mi][ni][j] = 0.f; Y[mi][ni][j] = 0.f; Z[mi][ni][j] = 0.f; }

    auto ldstage = [&](int s) {
        if (s < 6) {
            int buf = s & 1;
#pragma unroll
            for (int j = 0; j < 4; j++) {
                int lin = t + 256 * j;
                int row = lin >> 4;
                int c8 = (lin & 15) * 8;
                int n = n0 + row;
                if (n >= NN) n = 0;
                cpa16(Ah + buf * 64 * STR + row * STR + c8,
                      g_aggH + ((size_t)s * NN + n) * FF + c8);
            }
#pragma unroll
            for (int j = 0; j < 8; j++) {
                int lin = t + 256 * j;
                int o = lin >> 4;
                int c8 = (lin & 15) * 8;
                cpa16(Bw + buf * 128 * STR + o * STR + c8,
                      g_Wh + (size_t)s * (FF * FF) + o * FF + c8);
            }
        } else {
#pragma unroll
            for (int j = 0; j < 8; j++) {
                int lin = t + 256 * j;
                int o = lin >> 4;
                int c8 = (lin & 15) * 8;
                cpa16(Bw + o * STR + c8, g_Wc1h + o * FF + c8);
            }
#pragma unroll
            for (int j = 0; j < 8; j++) {
                int lin = t + 256 * j;
                int o = lin >> 4;
                int c8 = (lin & 15) * 8;
                cpa16(Wc2s + o * STR + c8, g_Wc2h + o * FF + c8);
            }
        }
        asm volatile("cp.async.commit_group;" ::: "memory");
    };

    auto mmastep = [&](const __half* Abase, const __half* Bbase) {
#pragma unroll
        for (int ks = 0; ks < 8; ks++) {
            int k0 = ks * 16;
            uint32_t a[2][4];
#pragma unroll
            for (int mi = 0; mi < 2; mi++) {
                const __half* ap = Abase + (wm * 32 + mi * 16 + g) * STR + k0 + tg * 2;
                a[mi][0] = *reinterpret_cast<const uint32_t*>(ap);
                a[mi][1] = *reinterpret_cast<const uint32_t*>(ap + 8 * STR);
                a[mi][2] = *reinterpret_cast<const uint32_t*>(ap + 8);
                a[mi][3] = *reinterpret_cast<const uint32_t*>(ap + 8 * STR + 8);
            }
            uint32_t b[4][2];
#pragma unroll
            for (int ni = 0; ni < 4; ni++) {
                const __half* bp = Bbase + (wn * 32 + ni * 8 + g) * STR + k0 + tg * 2;
                b[ni][0] = *reinterpret_cast<const uint32_t*>(bp);
                b[ni][1] = *reinterpret_cast<const uint32_t*>(bp + 8);
            }
#pragma unroll
            for (int mi = 0; mi < 2; mi++)
#pragma unroll
                for (int ni = 0; ni < 4; ni++)
                    mma16(P[mi][ni], a[mi][0], a[mi][1], a[mi][2], a[mi][3],
                          b[ni][0], b[ni][1]);
        }
    };

    ldstage(0);
    ldstage(1);

    for (int s = 0; s < 6; s++) {
        asm volatile("cp.async.wait_group 1;" ::: "memory");
        __syncthreads();
        int buf = s & 1;
        mmastep(Ah + buf * 64 * STR, Bw + buf * 128 * STR);
#pragma unroll
        for (int mi = 0; mi < 2; mi++) {
            int ra = n0 + wm * 32 + mi * 16 + g;
            int rb = ra + 8;
            float c1a = (ra < NN) ? g_c1[ra * RR + s] : 0.f;
            float c1b = (rb < NN) ? g_c1[rb * RR + s] : 0.f;
            float c2a = (ra < NN) ? g_c2[ra * RR + s] : 0.f;
            float c2b = (rb < NN) ? g_c2[rb * RR + s] : 0.f;
#pragma unroll
            for (int ni = 0; ni < 4; ni++) {
                Y[mi][ni][0] += c1a * P[mi][ni][0];
                Y[mi][ni][1] += c1a * P[mi][ni][1];
                Y[mi][ni][2] += c1b * P[mi][ni][2];
                Y[mi][ni][3] += c1b * P[mi][ni][3];
                Z[mi][ni][0] += c2a * P[mi][ni][0];
                Z[mi][ni][1] += c2a * P[mi][ni][1];
                Z[mi][ni][2] += c2b * P[mi][ni][2];
                Z[mi][ni][3] += c2b * P[mi][ni][3];
                P[mi][ni][0] = 0.f; P[mi][ni][1] = 0.f;
                P[mi][ni][2] = 0.f; P[mi][ni][3] = 0.f;
            }
        }
        __syncthreads();
        if (s + 2 <= 6) ldstage(s + 2);
    }

    asm volatile("cp.async.wait_group 0;" ::: "memory");

#pragma unroll
    for (int mi = 0; mi < 2; mi++) {
        int row = wm * 32 + mi * 16 + g;
#pragma unroll
        for (int ni = 0; ni < 4; ni++) {
            int col = wn * 32 + ni * 8 + tg * 2;
            *reinterpret_cast<__half2*>(Yz + row * STR + col) =
                __floats2half2_rn(Y[mi][ni][0], Y[mi][ni][1]);
            *reinterpret_cast<__half2*>(Yz + (row + 8) * STR + col) =
                __floats2half2_rn(Y[mi][ni][2], Y[mi][ni][3]);
            *reinterpret_cast<__half2*>(Yz + 64 * STR + row * STR + col) =
                __floats2half2_rn(Z[mi][ni][0], Z[mi][ni][1]);
            *reinterpret_cast<__half2*>(Yz + 64 * STR + (row + 8) * STR + col) =
                __floats2half2_rn(Z[mi][ni][2], Z[mi][ni][3]);
        }
    }
    __syncthreads();

    mmastep(Yz, Bw);
    mmastep(Yz + 64 * STR, Wc2s);

#pragma unroll
    for (int mi = 0; mi < 2; mi++) {
        int ra = n0 + wm * 32 + mi * 16 + g;
#pragma unroll
        for (int ni = 0; ni < 4; ni++) {
            int col = wn * 32 + ni * 8 + tg * 2;
            float b0 = 6.0f * bc[col];
            float b1 = 6.0f * bc[col + 1];
            if (ra < NN) {
                float2 v = make_float2(P[mi][ni][0] + b0, P[mi][ni][1] + b1);
                *reinterpret_cast<float2*>(&out[(size_t)ra * FF + col]) = v;
            }
            if (ra + 8 < NN) {
                float2 v = make_float2(P[mi][ni][2] + b0, P[mi][ni][3] + b1);
                *reinterpret_cast<float2*>(&out[(size_t)(ra + 8) * FF + col]) = v;
            }
        }
    }
}

// ---------------- launch: multi-branch graph (fork/join via events) ----------------
extern "C" void kernel_launch(void* const* d_in, const int* in_sizes, int n_in,
                              void* d_out, int out_size) {
    const float* node_h = (const float*)d_in[0];
    const float* W      = (const float*)d_in[1];
    const float* att1   = (const float*)d_in[2];
    const float* att2   = (const float*)d_in[3];
    const float* Wc     = (const float*)d_in[4];
    const float* bc     = (const float*)d_in[5];
    const int*   esrc   = (const int*)d_in[6];
    const int*   edst   = (const int*)d_in[7];
    const int*   erel   = (const int*)d_in[8];
    float* out = (float*)d_out;

    static int inited = 0;
    static cudaStream_t s1;
    static cudaEvent_t evFork, evPre, evG[NCHUNK], evJoin;
    if (!inited) {
        cudaFuncSetAttribute(gemm_kernel, cudaFuncAttributeMaxDynamicSharedMemorySize, GEMM_SMEM);
        cudaStreamCreateWithFlags(&s1, cudaStreamNonBlocking);
        cudaEventCreateWithFlags(&evFork, cudaEventDisableTiming);
        cudaEventCreateWithFlags(&evPre, cudaEventDisableTiming);
        for (int c = 0; c < NCHUNK; c++)
            cudaEventCreateWithFlags(&evG[c], cudaEventDisableTiming);
        cudaEventCreateWithFlags(&evJoin, cudaEventDisableTiming);
        inited = 1;
    }

    const int nblk1 = (SEG + 511) / 512;

    // fork: precompute branch on s1
    cudaEventRecord(evFork, 0);
    cudaStreamWaitEvent(s1, evFork, 0);
    precompute_kernel<<<RR * FF, 128, 0, s1>>>(W, att1, att2);
    wc_convert_kernel<<<FF, 128, 0, s1>>>(Wc);
    nodeh_convert_kernel<<<(NN * FF / 8 + 255) / 256, 256, 0, s1>>>(node_h);
    cudaEventRecord(evPre, s1);

    // CSR branch on stream 0
    zero_cnt_kernel<<<(SEG + 255) / 256, 256>>>();
    hist_kernel<<<(EE + 255) / 256, 256>>>(edst, erel);
    scan1_kernel<<<nblk1, 512>>>();
    scan2_kernel<<<1, 1024>>>(nblk1);
    scan3_kernel<<<(SEG + 255) / 256, 256>>>();
    permute_kernel<<<(EE + 255) / 256, 256>>>(esrc, edst, erel);

    // join precompute before gather
    cudaStreamWaitEvent(0, evPre, 0);

    // pipelined gather/softmax (stream 0) -> gemm (s1)
    for (int c = 0; c < NCHUNK; c++) {
        int n0 = c * CHN;
        int cnt = (n0 + CHN <= NN) ? CHN : (NN - n0);
        gather_kernel<<<(RR * cnt + 7) / 8, 256>>>(n0, cnt);
        softmax_kernel<<<(cnt + 255) / 256, 256>>>(n0, cnt);
        cudaEventRecord(evG[c], 0);
        cudaStreamWaitEvent(s1, evG[c], 0);
        gemm_kernel<<<(cnt + 63) / 64, 256, GEMM_SMEM, s1>>>(out, bc, n0);
    }
    cudaEventRecord(evJoin, s1);
    cudaStreamWaitEvent(0, evJoin, 0);

    // pass-through second output: weight
    if (out_size >= NN * FF + RR * FF * FF) {
        cudaMemcpyAsync(out + (size_t)NN * FF, W,
                        sizeof(float) * RR * FF * FF, cudaMemcpyDeviceToDevice, 0);
    }
}

// round 10
// speedup vs baseline: 1.1388x; 1.1388x over previous
#include <cuda_runtime.h>
#include <cuda_fp16.h>
#include <cstdint>

#define NN 50000
#define EE 800000
#define RR 6
#define FF 128
#define SEG (RR * NN)

// ---------------- scratch (static device globals; no allocations) ----------------
__device__ __align__(16) __half g_nodeH[(size_t)NN * FF];  // 12.8 MB fp16 node_h
__device__ __align__(16) __half g_aggH[(size_t)SEG * FF];  // 76.8 MB fp16 agg
__device__ __align__(16) float g_c1[NN * RR];
__device__ __align__(16) float g_c2[NN * RR];
__device__ __align__(16) float g_v1[RR * FF];
__device__ __align__(16) float g_v2[RR * FF];
__device__ __align__(16) __half g_Wh[RR * FF * FF];        // [r][o][f] = W[r][f][o] fp16
__device__ __align__(16) __half g_Wc1h[FF * FF];           // [o][k] fp16
__device__ __align__(16) __half g_Wc2h[FF * FF];
__device__ __align__(16) float g_e1[SEG];
__device__ __align__(16) float g_e2[SEG];
__device__ __align__(16) int g_cnt[SEG];
__device__ __align__(16) int g_off[SEG];
__device__ __align__(16) int g_bsum[1024];
__device__ __align__(16) int g_src_sorted[EE];

__device__ __forceinline__ void cpa16(void* dst_smem, const void* src) {
    uint32_t d = (uint32_t)__cvta_generic_to_shared(dst_smem);
    asm volatile("cp.async.cg.shared.global [%0], [%1], 16;" :: "r"(d), "l"(src));
}

// ---------------- K0: precompute v1,v2 and fp16 W^T per relation ----------------
__global__ void precompute_kernel(const float* __restrict__ W,
                                  const float* __restrict__ att1,
                                  const float* __restrict__ att2) {
    __shared__ float red1[128];
    __shared__ float red2[128];
    int rf = blockIdx.x;           // r*128 + f
    int r  = rf >> 7, f = rf & 127;
    int o  = threadIdx.x;
    float w = W[rf * 128 + o];
    g_Wh[(size_t)r * (FF * FF) + o * FF + f] = __float2half_rn(w);

    red1[o] = w * att1[o];
    red2[o] = w * att2[o];
    __syncthreads();
    for (int s = 64; s > 0; s >>= 1) {
        if (o < s) { red1[o] += red1[o + s]; red2[o] += red2[o + s]; }
        __syncthreads();
    }
    if (o == 0) { g_v1[rf] = red1[0]; g_v2[rf] = red2[0]; }
}

__global__ void wc_convert_kernel(const float* __restrict__ Wc) {
    int o = blockIdx.x, k = threadIdx.x;
    g_Wc1h[o * FF + k] = __float2half_rn(Wc[o * 256 + k]);
    g_Wc2h[o * FF + k] = __float2half_rn(Wc[o * 256 + 128 + k]);
}

// ---------------- convert node_h -> fp16 ----------------
__global__ void nodeh_convert_kernel(const float* __restrict__ node_h) {
    size_t i = (size_t)blockIdx.x * blockDim.x + threadIdx.x;   // one per 8 elems
    if (i >= (size_t)NN * FF / 8) return;
    const float4* p = reinterpret_cast<const float4*>(node_h) + i * 2;
    float4 a = p[0], b = p[1];
    __half2 h0 = __floats2half2_rn(a.x, a.y);
    __half2 h1 = __floats2half2_rn(a.z, a.w);
    __half2 h2 = __floats2half2_rn(b.x, b.y);
    __half2 h3 = __floats2half2_rn(b.z, b.w);
    uint4 o;
    o.x = *reinterpret_cast<uint32_t*>(&h0);
    o.y = *reinterpret_cast<uint32_t*>(&h1);
    o.z = *reinterpret_cast<uint32_t*>(&h2);
    o.w = *reinterpret_cast<uint32_t*>(&h3);
    reinterpret_cast<uint4*>(g_nodeH)[i] = o;
}

// ---------------- CSR build ----------------
__global__ void hist_kernel(const int4* __restrict__ edst4, const int4* __restrict__ erel4) {
    int i = blockIdx.x * blockDim.x + threadIdx.x;
    if (i >= EE / 4) return;
    int4 d = edst4[i];
    int4 r = erel4[i];
    atomicAdd(&g_cnt[r.x * NN + d.x], 1);
    atomicAdd(&g_cnt[r.y * NN + d.y], 1);
    atomicAdd(&g_cnt[r.z * NN + d.z], 1);
    atomicAdd(&g_cnt[r.w * NN + d.w], 1);
}
__global__ void scan1_kernel() {
    __shared__ int sm[512];
    int tid = threadIdx.x;
    int idx = blockIdx.x * 512 + tid;
    int v = (idx < SEG) ? g_cnt[idx] : 0;
    sm[tid] = v;
    __syncthreads();
#pragma unroll
    for (int s = 1; s < 512; s <<= 1) {
        int add = (tid >= s) ? sm[tid - s] : 0;
        __syncthreads();
        sm[tid] += add;
        __syncthreads();
    }
    int incl = sm[tid];
    if (idx < SEG) g_off[idx] = incl - v;
    if (tid == 511) g_bsum[blockIdx.x] = incl;
}
__global__ void scan2_kernel(int nblk) {
    __shared__ int sm[1024];
    int tid = threadIdx.x;
    int v = (tid < nblk) ? g_bsum[tid] : 0;
    sm[tid] = v;
    __syncthreads();
#pragma unroll
    for (int s = 1; s < 1024; s <<= 1) {
        int add = (tid >= s) ? sm[tid - s] : 0;
        __syncthreads();
        sm[tid] += add;
        __syncthreads();
    }
    if (tid < nblk) g_bsum[tid] = sm[tid] - v;
}
__global__ void scan3_kernel() {
    int idx = blockIdx.x * blockDim.x + threadIdx.x;
    if (idx >= SEG) return;
    g_off[idx] += g_bsum[idx >> 9];
}
// permute consumes g_off as cursors (atomicAdd). g_off is fully recomputed by
// scan1/2/3 on every launch, so this is replay-safe. gather recovers the
// segment base as g_off[seg] - g_cnt[seg] (post-permute g_off = segment end).
__global__ void permute_kernel(const int4* __restrict__ esrc4,
                               const int4* __restrict__ edst4,
                               const int4* __restrict__ erel4) {
    int i = blockIdx.x * blockDim.x + threadIdx.x;
    if (i >= EE / 4) return;
    int4 s = esrc4[i];
    int4 d = edst4[i];
    int4 r = erel4[i];
    int p0 = atomicAdd(&g_off[r.x * NN + d.x], 1);
    int p1 = atomicAdd(&g_off[r.y * NN + d.y], 1);
    int p2 = atomicAdd(&g_off[r.z * NN + d.z], 1);
    int p3 = atomicAdd(&g_off[r.w * NN + d.w], 1);
    g_src_sorted[p0] = s.x;
    g_src_sorted[p1] = s.y;
    g_src_sorted[p2] = s.z;
    g_src_sorted[p3] = s.w;
}

// ---------------- gather: one warp per (rel,dst) segment; fp16 in, fp16 out ----------------
__global__ __launch_bounds__(256) void gather_kernel() {
    int seg = blockIdx.x * 8 + (threadIdx.x >> 5);
    if (seg >= SEG) return;
    int l = threadIdx.x & 31;
    int r = seg / NN;
    int deg = g_cnt[seg];
    int off = g_off[seg] - deg;      // post-permute g_off = segment end

    const uint2* h2 = reinterpret_cast<const uint2*>(g_nodeH);
    float4 acc = make_float4(0.f, 0.f, 0.f, 0.f);
    int e = 0;
    for (; e + 4 <= deg; e += 4) {
        int i0 = g_src_sorted[off + e];
        int i1 = g_src_sorted[off + e + 1];
        int i2 = g_src_sorted[off + e + 2];
        int i3 = g_src_sorted[off + e + 3];
        uint2 u0 = h2[(size_t)i0 * 32 + l];
        uint2 u1 = h2[(size_t)i1 * 32 + l];
        uint2 u2 = h2[(size_t)i2 * 32 + l];
        uint2 u3 = h2[(size_t)i3 * 32 + l];
        float2 a0 = __half22float2(*reinterpret_cast<__half2*>(&u0.x));
        float2 a1 = __half22float2(*reinterpret_cast<__half2*>(&u0.y));
        float2 b0 = __half22float2(*reinterpret_cast<__half2*>(&u1.x));
        float2 b1 = __half22float2(*reinterpret_cast<__half2*>(&u1.y));
        float2 c0 = __half22float2(*reinterpret_cast<__half2*>(&u2.x));
        float2 c1 = __half22float2(*reinterpret_cast<__half2*>(&u2.y));
        float2 d0 = __half22float2(*reinterpret_cast<__half2*>(&u3.x));
        float2 d1 = __half22float2(*reinterpret_cast<__half2*>(&u3.y));
        acc.x += (a0.x + b0.x) + (c0.x + d0.x);
        acc.y += (a0.y + b0.y) + (c0.y + d0.y);
        acc.z += (a1.x + b1.x) + (c1.x + d1.x);
        acc.w += (a1.y + b1.y) + (c1.y + d1.y);
    }
    for (; e < deg; e++) {
        int i0 = g_src_sorted[off + e];
        uint2 ua = h2[(size_t)i0 * 32 + l];
        float2 a0 = __half22float2(*reinterpret_cast<__half2*>(&ua.x));
        float2 a1 = __half22float2(*reinterpret_cast<__half2*>(&ua.y));
        acc.x += a0.x; acc.y += a0.y; acc.z += a1.x; acc.w += a1.y;
    }

    __half2 h01 = __floats2half2_rn(acc.x, acc.y);
    __half2 h23 = __floats2half2_rn(acc.z, acc.w);
    uint2 packed;
    packed.x = *reinterpret_cast<uint32_t*>(&h01);
    packed.y = *reinterpret_cast<uint32_t*>(&h23);
    reinterpret_cast<uint2*>(g_aggH)[(size_t)seg * 32 + l] = packed;

    float4 w1 = reinterpret_cast<const float4*>(g_v1)[r * 32 + l];
    float4 w2 = reinterpret_cast<const float4*>(g_v2)[r * 32 + l];
    float p1 = acc.x * w1.x + acc.y * w1.y + acc.z * w1.z + acc.w * w1.w;
    float p2 = acc.x * w2.x + acc.y * w2.y + acc.z * w2.z + acc.w * w2.w;
#pragma unroll
    for (int s = 16; s > 0; s >>= 1) {
        p1 += __shfl_xor_sync(0xffffffffu, p1, s);
        p2 += __shfl_xor_sync(0xffffffffu, p2, s);
    }
    if (l == 0) { g_e1[seg] = p1; g_e2[seg] = p2; }
}

// ---------------- per-node softmax -> c1,c2 ----------------
__global__ void softmax_kernel() {
    int n = blockIdx.x * blockDim.x + threadIdx.x;
    if (n >= NN) return;
    float e1[RR], e2[RR], dg[RR];
#pragma unroll
    for (int r = 0; r < RR; r++) {
        dg[r] = 1.0f + (float)g_cnt[r * NN + n];
        e1[r] = g_e1[r * NN + n] / dg[r];
        e2[r] = g_e2[r * NN + n] / dg[r];
    }
    float m1 = e1[0], m2 = e2[0];
#pragma unroll
    for (int r = 1; r < RR; r++) { m1 = fmaxf(m1, e1[r]); m2 = fmaxf(m2, e2[r]); }
    float s1 = 0.f, s2 = 0.f;
#pragma unroll
    for (int r = 0; r < RR; r++) {
        e1[r] = __expf(e1[r] - m1); s1 += e1[r];
        e2[r] = __expf(e2[r] - m2); s2 += e2[r];
    }
    float i1 = 1.0f / s1, i2 = 1.0f / s2;
#pragma unroll
    for (int r = 0; r < RR; r++) {
        g_c1[n * RR + r] = e1[r] * i1 / dg[r];
        g_c2[n * RR + r] = e2[r] * i2 / dg[r];
    }
}

// ---------------- K4: fused factored GEMM ----------------
__device__ __forceinline__ void mma16(float d[4], uint32_t a0, uint32_t a1, uint32_t a2, uint32_t a3,
                                      uint32_t b0, uint32_t b1) {
    asm volatile(
        "mma.sync.aligned.m16n8k16.row.col.f32.f16.f16.f32 "
        "{%0,%1,%2,%3},{%4,%5,%6,%7},{%8,%9},{%0,%1,%2,%3};"
        : "+f"(d[0]), "+f"(d[1]), "+f"(d[2]), "+f"(d[3])
        : "r"(a0), "r"(a1), "r"(a2), "r"(a3), "r"(b0), "r"(b1));
}

#define STR 136
#define AH_OFF 0
#define BW_OFF (2 * 64 * STR)
#define YZ_OFF (BW_OFF + 2 * 128 * STR)
#define WC2_OFF (YZ_OFF + 2 * 64 * STR)
#define GEMM_SMEM ((WC2_OFF + 128 * STR) * 2)   // 174080 bytes

__global__ __launch_bounds__(256, 1) void gemm_kernel(float* __restrict__ out,
                                                      const float* __restrict__ bc) {
    extern __shared__ __half sh[];
    __half* Ah   = sh + AH_OFF;    // [2][64][STR]
    __half* Bw   = sh + BW_OFF;    // [2][128][STR]
    __half* Yz   = sh + YZ_OFF;    // [2][64][STR]
    __half* Wc2s = sh + WC2_OFF;   // [128][STR]

    int n0 = blockIdx.x * 64;
    int t = threadIdx.x;
    int warp = t >> 5, lane = t & 31;
    int wm = warp >> 2, wn = warp & 3;   // 2x4 warps, warp tile 32 rows x 32 cols
    int g = lane >> 2, tg = lane & 3;

    float P[2][4][4], Y[2][4][4], Z[2][4][4];
#pragma unroll
    for (int mi = 0; mi < 2; mi++)
#pragma unroll
        for (int ni = 0; ni < 4; ni++)
#pragma unroll
            for (int j = 0; j < 4; j++) { P[mi][ni][j] = 0.f; Y[mi][ni][j] = 0.f; Z[mi][ni][j] = 0.f; }

    auto ldstage = [&](int s) {
        if (s < 6) {
            int buf = s & 1;
#pragma unroll
            for (int j = 0; j < 4; j++) {                 // A tile: 64x128 halves
                int lin = t + 256 * j;
                int row = lin >> 4;
                int c8 = (lin & 15) * 8;
                int n = n0 + row;
                if (n >= NN) n = 0;
                cpa16(Ah + buf * 64 * STR + row * STR + c8,
                      g_aggH + ((size_t)s * NN + n) * FF + c8);
            }
#pragma unroll
            for (int j = 0; j < 8; j++) {                 // W tile: 128x128 halves
                int lin = t + 256 * j;
                int o = lin >> 4;
                int c8 = (lin & 15) * 8;
                cpa16(Bw + buf * 128 * STR + o * STR + c8,
                      g_Wh + (size_t)s * (FF * FF) + o * FF + c8);
            }
        } else {
#pragma unroll
            for (int j = 0; j < 8; j++) {                 // Wc1 -> Bw[0]
                int lin = t + 256 * j;
                int o = lin >> 4;
                int c8 = (lin & 15) * 8;
                cpa16(Bw + o * STR + c8, g_Wc1h + o * FF + c8);
            }
#pragma unroll
            for (int j = 0; j < 8; j++) {                 // Wc2 -> Wc2s
                int lin = t + 256 * j;
                int o = lin >> 4;
                int c8 = (lin & 15) * 8;
                cpa16(Wc2s + o * STR + c8, g_Wc2h + o * FF + c8);
            }
        }
        asm volatile("cp.async.commit_group;" ::: "memory");
    };

    auto mmastep = [&](const __half* Abase, const __half* Bbase) {
#pragma unroll
        for (int ks = 0; ks < 8; ks++) {
            int k0 = ks * 16;
            uint32_t a[2][4];
#pragma unroll
            for (int mi = 0; mi < 2; mi++) {
                const __half* ap = Abase + (wm * 32 + mi * 16 + g) * STR + k0 + tg * 2;
                a[mi][0] = *reinterpret_cast<const uint32_t*>(ap);
                a[mi][1] = *reinterpret_cast<const uint32_t*>(ap + 8 * STR);
                a[mi][2] = *reinterpret_cast<const uint32_t*>(ap + 8);
                a[mi][3] = *reinterpret_cast<const uint32_t*>(ap + 8 * STR + 8);
            }
            uint32_t b[4][2];
#pragma unroll
            for (int ni = 0; ni < 4; ni++) {
                const __half* bp = Bbase + (wn * 32 + ni * 8 + g) * STR + k0 + tg * 2;
                b[ni][0] = *reinterpret_cast<const uint32_t*>(bp);
                b[ni][1] = *reinterpret_cast<const uint32_t*>(bp + 8);
            }
#pragma unroll
            for (int mi = 0; mi < 2; mi++)
#pragma unroll
                for (int ni = 0; ni < 4; ni++)
                    mma16(P[mi][ni], a[mi][0], a[mi][1], a[mi][2], a[mi][3],
                          b[ni][0], b[ni][1]);
        }
    };

    ldstage(0);
    ldstage(1);

    for (int s = 0; s < 6; s++) {
        asm volatile("cp.async.wait_group 1;" ::: "memory");
        __syncthreads();
        int buf = s & 1;
        mmastep(Ah + buf * 64 * STR, Bw + buf * 128 * STR);
#pragma unroll
        for (int mi = 0; mi < 2; mi++) {
            int ra = n0 + wm * 32 + mi * 16 + g;
            int rb = ra + 8;
            float c1a = (ra < NN) ? g_c1[ra * RR + s] : 0.f;
            float c1b = (rb < NN) ? g_c1[rb * RR + s] : 0.f;
            float c2a = (ra < NN) ? g_c2[ra * RR + s] : 0.f;
            float c2b = (rb < NN) ? g_c2[rb * RR + s] : 0.f;
#pragma unroll
            for (int ni = 0; ni < 4; ni++) {
                Y[mi][ni][0] += c1a * P[mi][ni][0];
                Y[mi][ni][1] += c1a * P[mi][ni][1];
                Y[mi][ni][2] += c1b * P[mi][ni][2];
                Y[mi][ni][3] += c1b * P[mi][ni][3];
                Z[mi][ni][0] += c2a * P[mi][ni][0];
                Z[mi][ni][1] += c2a * P[mi][ni][1];
                Z[mi][ni][2] += c2b * P[mi][ni][2];
                Z[mi][ni][3] += c2b * P[mi][ni][3];
                P[mi][ni][0] = 0.f; P[mi][ni][1] = 0.f;
                P[mi][ni][2] = 0.f; P[mi][ni][3] = 0.f;
            }
        }
        __syncthreads();
        if (s + 2 <= 6) ldstage(s + 2);
    }

    asm volatile("cp.async.wait_group 0;" ::: "memory");

#pragma unroll
    for (int mi = 0; mi < 2; mi++) {
        int row = wm * 32 + mi * 16 + g;
#pragma unroll
        for (int ni = 0; ni < 4; ni++) {
            int col = wn * 32 + ni * 8 + tg * 2;
            *reinterpret_cast<__half2*>(Yz + row * STR + col) =
                __floats2half2_rn(Y[mi][ni][0], Y[mi][ni][1]);
            *reinterpret_cast<__half2*>(Yz + (row + 8) * STR + col) =
                __floats2half2_rn(Y[mi][ni][2], Y[mi][ni][3]);
            *reinterpret_cast<__half2*>(Yz + 64 * STR + row * STR + col) =
                __floats2half2_rn(Z[mi][ni][0], Z[mi][ni][1]);
            *reinterpret_cast<__half2*>(Yz + 64 * STR + (row + 8) * STR + col) =
                __floats2half2_rn(Z[mi][ni][2], Z[mi][ni][3]);
        }
    }
    __syncthreads();

    mmastep(Yz, Bw);                 // Y @ Wc1^T
    mmastep(Yz + 64 * STR, Wc2s);    // Z @ Wc2^T

#pragma unroll
    for (int mi = 0; mi < 2; mi++) {
        int ra = n0 + wm * 32 + mi * 16 + g;
#pragma unroll
        for (int ni = 0; ni < 4; ni++) {
            int col = wn * 32 + ni * 8 + tg * 2;
            float b0 = 6.0f * bc[col];
            float b1 = 6.0f * bc[col + 1];
            if (ra < NN) {
                float2 v = make_float2(P[mi][ni][0] + b0, P[mi][ni][1] + b1);
                *reinterpret_cast<float2*>(&out[(size_t)ra * FF + col]) = v;
            }
            if (ra + 8 < NN) {
                float2 v = make_float2(P[mi][ni][2] + b0, P[mi][ni][3] + b1);
                *reinterpret_cast<float2*>(&out[(size_t)(ra + 8) * FF + col]) = v;
            }
        }
    }
}

// ---------------- launch ----------------
extern "C" void kernel_launch(void* const* d_in, const int* in_sizes, int n_in,
                              void* d_out, int out_size) {
    const float* node_h = (const float*)d_in[0];
    const float* W      = (const float*)d_in[1];
    const float* att1   = (const float*)d_in[2];
    const float* att2   = (const float*)d_in[3];
    const float* Wc     = (const float*)d_in[4];
    const float* bc     = (const float*)d_in[5];
    const int*   esrc   = (const int*)d_in[6];
    const int*   edst   = (const int*)d_in[7];
    const int*   erel   = (const int*)d_in[8];
    float* out = (float*)d_out;

    static int inited = 0;
    static cudaStream_t s1;
    static cudaEvent_t evFork, evPre;
    static void* cntAddr = nullptr;
    if (!inited) {
        cudaFuncSetAttribute(gemm_kernel, cudaFuncAttributeMaxDynamicSharedMemorySize, GEMM_SMEM);
        cudaStreamCreateWithFlags(&s1, cudaStreamNonBlocking);
        cudaEventCreateWithFlags(&evFork, cudaEventDisableTiming);
        cudaEventCreateWithFlags(&evPre, cudaEventDisableTiming);
        cudaGetSymbolAddress(&cntAddr, g_cnt);
        inited = 1;
    }

    const int nblk1 = (SEG + 511) / 512;

    // fork: precompute branch on s1 (independent of CSR build)
    cudaEventRecord(evFork, 0);
    cudaStreamWaitEvent(s1, evFork, 0);
    precompute_kernel<<<RR * FF, 128, 0, s1>>>(W, att1, att2);
    wc_convert_kernel<<<FF, 128, 0, s1>>>(Wc);
    nodeh_convert_kernel<<<(NN * FF / 8 + 255) / 256, 256, 0, s1>>>(node_h);
    cudaEventRecord(evPre, s1);

    // CSR branch on stream 0
    cudaMemsetAsync(cntAddr, 0, SEG * sizeof(int), 0);
    hist_kernel<<<(EE / 4 + 255) / 256, 256>>>((const int4*)edst, (const int4*)erel);
    scan1_kernel<<<nblk1, 512>>>();
    scan2_kernel<<<1, 1024>>>(nblk1);
    scan3_kernel<<<(SEG + 255) / 256, 256>>>();
    permute_kernel<<<(EE / 4 + 255) / 256, 256>>>((const int4*)esrc, (const int4*)edst,
                                                  (const int4*)erel);

    // join precompute before gather
    cudaStreamWaitEvent(0, evPre, 0);

    gather_kernel<<<(SEG + 7) / 8, 256>>>();
    softmax_kernel<<<(NN + 255) / 256, 256>>>();
    gemm_kernel<<<(NN + 63) / 64, 256, GEMM_SMEM>>>(out, bc);

    // pass-through second output: weight
    if (out_size >= NN * FF + RR * FF * FF) {
        cudaMemcpyAsync(out + (size_t)NN * FF, W,
                        sizeof(float) * RR * FF * FF, cudaMemcpyDeviceToDevice, 0);
    }
}

// round 11
// speedup vs baseline: 1.1493x; 1.0092x over previous
#include <cuda_runtime.h>
#include <cuda_fp16.h>
#include <cstdint>

#define NN 50000
#define EE 800000
#define RR 6
#define FF 128
#define SEG (RR * NN)

// ---------------- scratch (static device globals; no allocations) ----------------
__device__ __align__(16) __half g_nodeH[(size_t)NN * FF];  // 12.8 MB fp16 node_h
__device__ __align__(16) __half g_aggH[(size_t)SEG * FF];  // 76.8 MB fp16 agg
__device__ __align__(16) float g_v1[RR * FF];
__device__ __align__(16) float g_v2[RR * FF];
__device__ __align__(16) __half g_Wh[RR * FF * FF];        // [r][o][f] = W[r][f][o] fp16
__device__ __align__(16) __half g_Wc1h[FF * FF];           // [o][k] fp16
__device__ __align__(16) __half g_Wc2h[FF * FF];
__device__ __align__(16) float g_e1[SEG];
__device__ __align__(16) float g_e2[SEG];
__device__ __align__(16) int g_cnt[SEG];
__device__ __align__(16) int g_off[SEG];
__device__ __align__(16) int g_bsum[1024];
__device__ __align__(16) int g_src_sorted[EE];

__device__ __forceinline__ void cpa16(void* dst_smem, const void* src) {
    uint32_t d = (uint32_t)__cvta_generic_to_shared(dst_smem);
    asm volatile("cp.async.cg.shared.global [%0], [%1], 16;" :: "r"(d), "l"(src));
}

// ---------------- K0: precompute v1,v2 and fp16 W^T per relation ----------------
__global__ void precompute_kernel(const float* __restrict__ W,
                                  const float* __restrict__ att1,
                                  const float* __restrict__ att2) {
    __shared__ float red1[128];
    __shared__ float red2[128];
    int rf = blockIdx.x;           // r*128 + f
    int r  = rf >> 7, f = rf & 127;
    int o  = threadIdx.x;
    float w = W[rf * 128 + o];
    g_Wh[(size_t)r * (FF * FF) + o * FF + f] = __float2half_rn(w);

    red1[o] = w * att1[o];
    red2[o] = w * att2[o];
    __syncthreads();
    for (int s = 64; s > 0; s >>= 1) {
        if (o < s) { red1[o] += red1[o + s]; red2[o] += red2[o + s]; }
        __syncthreads();
    }
    if (o == 0) { g_v1[rf] = red1[0]; g_v2[rf] = red2[0]; }
}

__global__ void wc_convert_kernel(const float* __restrict__ Wc) {
    int o = blockIdx.x, k = threadIdx.x;
    g_Wc1h[o * FF + k] = __float2half_rn(Wc[o * 256 + k]);
    g_Wc2h[o * FF + k] = __float2half_rn(Wc[o * 256 + 128 + k]);
}

// ---------------- convert node_h -> fp16 ----------------
__global__ void nodeh_convert_kernel(const float* __restrict__ node_h) {
    size_t i = (size_t)blockIdx.x * blockDim.x + threadIdx.x;   // one per 8 elems
    if (i >= (size_t)NN * FF / 8) return;
    const float4* p = reinterpret_cast<const float4*>(node_h) + i * 2;
    float4 a = p[0], b = p[1];
    __half2 h0 = __floats2half2_rn(a.x, a.y);
    __half2 h1 = __floats2half2_rn(a.z, a.w);
    __half2 h2 = __floats2half2_rn(b.x, b.y);
    __half2 h3 = __floats2half2_rn(b.z, b.w);
    uint4 o;
    o.x = *reinterpret_cast<uint32_t*>(&h0);
    o.y = *reinterpret_cast<uint32_t*>(&h1);
    o.z = *reinterpret_cast<uint32_t*>(&h2);
    o.w = *reinterpret_cast<uint32_t*>(&h3);
    reinterpret_cast<uint4*>(g_nodeH)[i] = o;
}

// ---------------- CSR build ----------------
__global__ void hist_kernel(const int4* __restrict__ edst4, const int4* __restrict__ erel4) {
    int i = blockIdx.x * blockDim.x + threadIdx.x;
    if (i >= EE / 4) return;
    int4 d = edst4[i];
    int4 r = erel4[i];
    atomicAdd(&g_cnt[r.x * NN + d.x], 1);
    atomicAdd(&g_cnt[r.y * NN + d.y], 1);
    atomicAdd(&g_cnt[r.z * NN + d.z], 1);
    atomicAdd(&g_cnt[r.w * NN + d.w], 1);
}
__global__ void scan1_kernel() {
    __shared__ int sm[512];
    int tid = threadIdx.x;
    int idx = blockIdx.x * 512 + tid;
    int v = (idx < SEG) ? g_cnt[idx] : 0;
    sm[tid] = v;
    __syncthreads();
#pragma unroll
    for (int s = 1; s < 512; s <<= 1) {
        int add = (tid >= s) ? sm[tid - s] : 0;
        __syncthreads();
        sm[tid] += add;
        __syncthreads();
    }
    int incl = sm[tid];
    if (idx < SEG) g_off[idx] = incl - v;
    if (tid == 511) g_bsum[blockIdx.x] = incl;
}
__global__ void scan2_kernel(int nblk) {
    __shared__ int sm[1024];
    int tid = threadIdx.x;
    int v = (tid < nblk) ? g_bsum[tid] : 0;
    sm[tid] = v;
    __syncthreads();
#pragma unroll
    for (int s = 1; s < 1024; s <<= 1) {
        int add = (tid >= s) ? sm[tid - s] : 0;
        __syncthreads();
        sm[tid] += add;
        __syncthreads();
    }
    if (tid < nblk) g_bsum[tid] = sm[tid] - v;
}
__global__ void scan3_kernel() {
    int idx = blockIdx.x * blockDim.x + threadIdx.x;
    if (idx >= SEG) return;
    g_off[idx] += g_bsum[idx >> 9];
}
// permute consumes g_off as cursors (atomicAdd); g_off is recomputed each launch.
// gather recovers the segment base as g_off[seg] - g_cnt[seg].
__global__ void permute_kernel(const int4* __restrict__ esrc4,
                               const int4* __restrict__ edst4,
                               const int4* __restrict__ erel4) {
    int i = blockIdx.x * blockDim.x + threadIdx.x;
    if (i >= EE / 4) return;
    int4 s = esrc4[i];
    int4 d = edst4[i];
    int4 r = erel4[i];
    int p0 = atomicAdd(&g_off[r.x * NN + d.x], 1);
    int p1 = atomicAdd(&g_off[r.y * NN + d.y], 1);
    int p2 = atomicAdd(&g_off[r.z * NN + d.z], 1);
    int p3 = atomicAdd(&g_off[r.w * NN + d.w], 1);
    g_src_sorted[p0] = s.x;
    g_src_sorted[p1] = s.y;
    g_src_sorted[p2] = s.z;
    g_src_sorted[p3] = s.w;
}

// ---------------- gather: one warp per (rel,dst) segment; fp16 in, fp16 out ----------------
__global__ __launch_bounds__(256) void gather_kernel() {
    int seg = blockIdx.x * 8 + (threadIdx.x >> 5);
    if (seg >= SEG) return;
    int l = threadIdx.x & 31;
    int r = seg / NN;
    int deg = g_cnt[seg];
    int off = g_off[seg] - deg;

    const uint2* h2 = reinterpret_cast<const uint2*>(g_nodeH);
    float4 acc = make_float4(0.f, 0.f, 0.f, 0.f);
    int e = 0;
    for (; e + 4 <= deg; e += 4) {
        int i0 = g_src_sorted[off + e];
        int i1 = g_src_sorted[off + e + 1];
        int i2 = g_src_sorted[off + e + 2];
        int i3 = g_src_sorted[off + e + 3];
        uint2 u0 = h2[(size_t)i0 * 32 + l];
        uint2 u1 = h2[(size_t)i1 * 32 + l];
        uint2 u2 = h2[(size_t)i2 * 32 + l];
        uint2 u3 = h2[(size_t)i3 * 32 + l];
        float2 a0 = __half22float2(*reinterpret_cast<__half2*>(&u0.x));
        float2 a1 = __half22float2(*reinterpret_cast<__half2*>(&u0.y));
        float2 b0 = __half22float2(*reinterpret_cast<__half2*>(&u1.x));
        float2 b1 = __half22float2(*reinterpret_cast<__half2*>(&u1.y));
        float2 c0 = __half22float2(*reinterpret_cast<__half2*>(&u2.x));
        float2 c1 = __half22float2(*reinterpret_cast<__half2*>(&u2.y));
        float2 d0 = __half22float2(*reinterpret_cast<__half2*>(&u3.x));
        float2 d1 = __half22float2(*reinterpret_cast<__half2*>(&u3.y));
        acc.x += (a0.x + b0.x) + (c0.x + d0.x);
        acc.y += (a0.y + b0.y) + (c0.y + d0.y);
        acc.z += (a1.x + b1.x) + (c1.x + d1.x);
        acc.w += (a1.y + b1.y) + (c1.y + d1.y);
    }
    for (; e < deg; e++) {
        int i0 = g_src_sorted[off + e];
        uint2 ua = h2[(size_t)i0 * 32 + l];
        float2 a0 = __half22float2(*reinterpret_cast<__half2*>(&ua.x));
        float2 a1 = __half22float2(*reinterpret_cast<__half2*>(&ua.y));
        acc.x += a0.x; acc.y += a0.y; acc.z += a1.x; acc.w += a1.y;
    }

    __half2 h01 = __floats2half2_rn(acc.x, acc.y);
    __half2 h23 = __floats2half2_rn(acc.z, acc.w);
    uint2 packed;
    packed.x = *reinterpret_cast<uint32_t*>(&h01);
    packed.y = *reinterpret_cast<uint32_t*>(&h23);
    reinterpret_cast<uint2*>(g_aggH)[(size_t)seg * 32 + l] = packed;

    float4 w1 = reinterpret_cast<const float4*>(g_v1)[r * 32 + l];
    float4 w2 = reinterpret_cast<const float4*>(g_v2)[r * 32 + l];
    float p1 = acc.x * w1.x + acc.y * w1.y + acc.z * w1.z + acc.w * w1.w;
    float p2 = acc.x * w2.x + acc.y * w2.y + acc.z * w2.z + acc.w * w2.w;
#pragma unroll
    for (int s = 16; s > 0; s >>= 1) {
        p1 += __shfl_xor_sync(0xffffffffu, p1, s);
        p2 += __shfl_xor_sync(0xffffffffu, p2, s);
    }
    if (l == 0) { g_e1[seg] = p1; g_e2[seg] = p2; }
}

// ---------------- K4: fused softmax + factored GEMM (2 blocks/SM) ----------------
__device__ __forceinline__ void mma16(float d[4], uint32_t a0, uint32_t a1, uint32_t a2, uint32_t a3,
                                      uint32_t b0, uint32_t b1) {
    asm volatile(
        "mma.sync.aligned.m16n8k16.row.col.f32.f16.f16.f32 "
        "{%0,%1,%2,%3},{%4,%5,%6,%7},{%8,%9},{%0,%1,%2,%3};"
        : "+f"(d[0]), "+f"(d[1]), "+f"(d[2]), "+f"(d[3])
        : "r"(a0), "r"(a1), "r"(a2), "r"(a3), "r"(b0), "r"(b1));
}

#define STR 136
#define AH_OFF 0                         // [2][64][STR] halves; Y/Z alias this after stage 1
#define BW_OFF (2 * 64 * STR)            // [128][STR] single-buffered W
#define WC2_OFF (BW_OFF + 128 * STR)     // [128][STR]
#define CS_OFF (WC2_OFF + 128 * STR)     // float c1s[384], c2s[384]
#define GEMM_SMEM (CS_OFF * 2 + 768 * 4) // 107520 bytes

__global__ __launch_bounds__(256, 2) void gemm_kernel(float* __restrict__ out,
                                                      const float* __restrict__ bc) {
    extern __shared__ __half sh[];
    __half* Ah   = sh + AH_OFF;
    __half* Bw   = sh + BW_OFF;
    __half* Wc2s = sh + WC2_OFF;
    float* c1s = reinterpret_cast<float*>(sh + CS_OFF);
    float* c2s = c1s + 384;

    int n0 = blockIdx.x * 64;
    int t = threadIdx.x;
    int warp = t >> 5, lane = t & 31;
    int wm = warp >> 2, wn = warp & 3;   // 2x4 warps, warp tile 32 rows x 32 cols
    int g = lane >> 2, tg = lane & 3;
    int rowa = wm * 32 + g;              // rows: rowa+mi*16 and +8

    auto ldA = [&](int s, int buf) {
#pragma unroll
        for (int j = 0; j < 4; j++) {
            int lin = t + 256 * j;
            int row = lin >> 4;
            int c8 = (lin & 15) * 8;
            int n = n0 + row;
            if (n >= NN) n = 0;
            cpa16(Ah + buf * 64 * STR + row * STR + c8,
                  g_aggH + ((size_t)s * NN + n) * FF + c8);
        }
    };
    auto ldW = [&](__half* dst, const __half* src) {
#pragma unroll
        for (int j = 0; j < 8; j++) {
            int lin = t + 256 * j;
            int o = lin >> 4;
            int c8 = (lin & 15) * 8;
            cpa16(dst + o * STR + c8, src + o * FF + c8);
        }
    };

    // prologue: G0 = {A0, W0}, G1 = {A1}
    ldA(0, 0); ldW(Bw, g_Wh);
    asm volatile("cp.async.commit_group;" ::: "memory");
    ldA(1, 1);
    asm volatile("cp.async.commit_group;" ::: "memory");

    // fused softmax: threads 0..63, one node each
    if (t < 64) {
        int n = n0 + t;
        if (n < NN) {
            float e1[RR], e2[RR], dg[RR];
#pragma unroll
            for (int r = 0; r < RR; r++) {
                dg[r] = 1.0f + (float)g_cnt[r * NN + n];
                e1[r] = g_e1[r * NN + n] / dg[r];
                e2[r] = g_e2[r * NN + n] / dg[r];
            }
            float m1 = e1[0], m2 = e2[0];
#pragma unroll
            for (int r = 1; r < RR; r++) { m1 = fmaxf(m1, e1[r]); m2 = fmaxf(m2, e2[r]); }
            float s1 = 0.f, s2 = 0.f;
#pragma unroll
            for (int r = 0; r < RR; r++) {
                e1[r] = __expf(e1[r] - m1); s1 += e1[r];
                e2[r] = __expf(e2[r] - m2); s2 += e2[r];
            }
            float i1 = 1.0f / s1, i2 = 1.0f / s2;
#pragma unroll
            for (int r = 0; r < RR; r++) {
                c1s[t * 6 + r] = e1[r] * i1 / dg[r];
                c2s[t * 6 + r] = e2[r] * i2 / dg[r];
            }
        } else {
#pragma unroll
            for (int r = 0; r < RR; r++) { c1s[t * 6 + r] = 0.f; c2s[t * 6 + r] = 0.f; }
        }
    }

    float P[2][4][4], Y[2][4][4], Z[2][4][4];
#pragma unroll
    for (int mi = 0; mi < 2; mi++)
#pragma unroll
        for (int ni = 0; ni < 4; ni++)
#pragma unroll
            for (int j = 0; j < 4; j++) { P[mi][ni][j] = 0.f; Y[mi][ni][j] = 0.f; Z[mi][ni][j] = 0.f; }

    auto mmastep = [&](const __half* Abase, const __half* Bbase) {
#pragma unroll
        for (int ks = 0; ks < 8; ks++) {
            int k0 = ks * 16;
            uint32_t a[2][4];
#pragma unroll
            for (int mi = 0; mi < 2; mi++) {
                const __half* ap = Abase + (rowa + mi * 16) * STR + k0 + tg * 2;
                a[mi][0] = *reinterpret_cast<const uint32_t*>(ap);
                a[mi][1] = *reinterpret_cast<const uint32_t*>(ap + 8 * STR);
                a[mi][2] = *reinterpret_cast<const uint32_t*>(ap + 8);
                a[mi][3] = *reinterpret_cast<const uint32_t*>(ap + 8 * STR + 8);
            }
            uint32_t b[4][2];
#pragma unroll
            for (int ni = 0; ni < 4; ni++) {
                const __half* bp = Bbase + (wn * 32 + ni * 8 + g) * STR + k0 + tg * 2;
                b[ni][0] = *reinterpret_cast<const uint32_t*>(bp);
                b[ni][1] = *reinterpret_cast<const uint32_t*>(bp + 8);
            }
#pragma unroll
            for (int mi = 0; mi < 2; mi++)
#pragma unroll
                for (int ni = 0; ni < 4; ni++)
                    mma16(P[mi][ni], a[mi][0], a[mi][1], a[mi][2], a[mi][3],
                          b[ni][0], b[ni][1]);
        }
    };

    for (int s = 0; s < 6; s++) {
        if (s == 5) { asm volatile("cp.async.wait_group 0;" ::: "memory"); }
        else        { asm volatile("cp.async.wait_group 1;" ::: "memory"); }
        __syncthreads();
        mmastep(Ah + (s & 1) * 64 * STR, Bw);
        if (s < 5) {
            __syncthreads();   // everyone done reading Bw and Ah[s&1]
            ldW(Bw, g_Wh + (size_t)(s + 1) * (FF * FF));
            asm volatile("cp.async.commit_group;" ::: "memory");  // GW_{s+1}
            if (s + 2 < 6) {
                ldA(s + 2, s & 1);
                asm volatile("cp.async.commit_group;" ::: "memory");  // GA_{s+2}
            }
        }
        // fold P into Y, Z
#pragma unroll
        for (int mi = 0; mi < 2; mi++) {
            int rl = rowa + mi * 16;
            float c1a = c1s[rl * 6 + s];
            float c1b = c1s[(rl + 8) * 6 + s];
            float c2a = c2s[rl * 6 + s];
            float c2b = c2s[(rl + 8) * 6 + s];
#pragma unroll
            for (int ni = 0; ni < 4; ni++) {
                Y[mi][ni][0] += c1a * P[mi][ni][0];
                Y[mi][ni][1] += c1a * P[mi][ni][1];
                Y[mi][ni][2] += c1b * P[mi][ni][2];
                Y[mi][ni][3] += c1b * P[mi][ni][3];
                Z[mi][ni][0] += c2a * P[mi][ni][0];
                Z[mi][ni][1] += c2a * P[mi][ni][1];
                Z[mi][ni][2] += c2b * P[mi][ni][2];
                Z[mi][ni][3] += c2b * P[mi][ni][3];
                P[mi][ni][0] = 0.f; P[mi][ni][1] = 0.f;
                P[mi][ni][2] = 0.f; P[mi][ni][3] = 0.f;
            }
        }
    }

    __syncthreads();   // all done reading A5/W5
    ldW(Bw, g_Wc1h);
    ldW(Wc2s, g_Wc2h);
    asm volatile("cp.async.commit_group;" ::: "memory");

    // stage Y,Z (fp16) into the A region (dead now)
    __half* Yt = Ah;
    __half* Zt = Ah + 64 * STR;
#pragma unroll
    for (int mi = 0; mi < 2; mi++) {
        int row = rowa + mi * 16;
#pragma unroll
        for (int ni = 0; ni < 4; ni++) {
            int col = wn * 32 + ni * 8 + tg * 2;
            *reinterpret_cast<__half2*>(Yt + row * STR + col) =
                __floats2half2_rn(Y[mi][ni][0], Y[mi][ni][1]);
            *reinterpret_cast<__half2*>(Yt + (row + 8) * STR + col) =
                __floats2half2_rn(Y[mi][ni][2], Y[mi][ni][3]);
            *reinterpret_cast<__half2*>(Zt + row * STR + col) =
                __floats2half2_rn(Z[mi][ni][0], Z[mi][ni][1]);
            *reinterpret_cast<__half2*>(Zt + (row + 8) * STR + col) =
                __floats2half2_rn(Z[mi][ni][2], Z[mi][ni][3]);
        }
    }
    asm volatile("cp.async.wait_group 0;" ::: "memory");
    __syncthreads();

    // stage 2: out = Y@Wc1^T + Z@Wc2^T  (P already zero)
    mmastep(Yt, Bw);
    mmastep(Zt, Wc2s);

#pragma unroll
    for (int mi = 0; mi < 2; mi++) {
        int ra = n0 + rowa + mi * 16;
#pragma unroll
        for (int ni = 0; ni < 4; ni++) {
            int col = wn * 32 + ni * 8 + tg * 2;
            float b0 = 6.0f * bc[col];
            float b1 = 6.0f * bc[col + 1];
            if (ra < NN) {
                float2 v = make_float2(P[mi][ni][0] + b0, P[mi][ni][1] + b1);
                *reinterpret_cast<float2*>(&out[(size_t)ra * FF + col]) = v;
            }
            if (ra + 8 < NN) {
                float2 v = make_float2(P[mi][ni][2] + b0, P[mi][ni][3] + b1);
                *reinterpret_cast<float2*>(&out[(size_t)(ra + 8) * FF + col]) = v;
            }
        }
    }
}

// ---------------- launch ----------------
extern "C" void kernel_launch(void* const* d_in, const int* in_sizes, int n_in,
                              void* d_out, int out_size) {
    const float* node_h = (const float*)d_in[0];
    const float* W      = (const float*)d_in[1];
    const float* att1   = (const float*)d_in[2];
    const float* att2   = (const float*)d_in[3];
    const float* Wc     = (const float*)d_in[4];
    const float* bc     = (const float*)d_in[5];
    const int*   esrc   = (const int*)d_in[6];
    const int*   edst   = (const int*)d_in[7];
    const int*   erel   = (const int*)d_in[8];
    float* out = (float*)d_out;

    static int inited = 0;
    static cudaStream_t s1;
    static cudaEvent_t evFork, evPre;
    static void* cntAddr = nullptr;
    if (!inited) {
        cudaFuncSetAttribute(gemm_kernel, cudaFuncAttributeMaxDynamicSharedMemorySize, GEMM_SMEM);
        cudaStreamCreateWithFlags(&s1, cudaStreamNonBlocking);
        cudaEventCreateWithFlags(&evFork, cudaEventDisableTiming);
        cudaEventCreateWithFlags(&evPre, cudaEventDisableTiming);
        cudaGetSymbolAddress(&cntAddr, g_cnt);
        inited = 1;
    }

    const int nblk1 = (SEG + 511) / 512;

    // fork: precompute branch on s1 (independent of CSR build)
    cudaEventRecord(evFork, 0);
    cudaStreamWaitEvent(s1, evFork, 0);
    if (out_size >= NN * FF + RR * FF * FF) {
        cudaMemcpyAsync(out + (size_t)NN * FF, W,
                        sizeof(float) * RR * FF * FF, cudaMemcpyDeviceToDevice, s1);
    }
    precompute_kernel<<<RR * FF, 128, 0, s1>>>(W, att1, att2);
    wc_convert_kernel<<<FF, 128, 0, s1>>>(Wc);
    nodeh_convert_kernel<<<(NN * FF / 8 + 255) / 256, 256, 0, s1>>>(node_h);
    cudaEventRecord(evPre, s1);

    // CSR branch on stream 0
    cudaMemsetAsync(cntAddr, 0, SEG * sizeof(int), 0);
    hist_kernel<<<(EE / 4 + 255) / 256, 256>>>((const int4*)edst, (const int4*)erel);
    scan1_kernel<<<nblk1, 512>>>();
    scan2_kernel<<<1, 1024>>>(nblk1);
    scan3_kernel<<<(SEG + 255) / 256, 256>>>();
    permute_kernel<<<(EE / 4 + 255) / 256, 256>>>((const int4*)esrc, (const int4*)edst,
                                                  (const int4*)erel);

    // join precompute before gather
    cudaStreamWaitEvent(0, evPre, 0);

    gather_kernel<<<(SEG + 7) / 8, 256>>>();
    gemm_kernel<<<(NN + 63) / 64, 256, GEMM_SMEM>>>(out, bc);
}

// round 12
// speedup vs baseline: 1.1760x; 1.0232x over previous
#include <cuda_runtime.h>
#include <cuda_fp16.h>
#include <cstdint>

#define NN 50000
#define EE 800000
#define RR 6
#define FF 128
#define SEG (RR * NN)

// ---------------- scratch (static device globals; no allocations) ----------------
__device__ __align__(16) __half g_nodeH[(size_t)NN * FF];  // 12.8 MB fp16 node_h
__device__ __align__(16) __half g_aggH[(size_t)SEG * FF];  // 76.8 MB fp16 agg
__device__ __align__(16) float g_v1[RR * FF];
__device__ __align__(16) float g_v2[RR * FF];
__device__ __align__(16) __half g_Wh[RR * FF * FF];        // [r][o][f] = W[r][f][o] fp16
__device__ __align__(16) __half g_Wc1h[FF * FF];           // [o][k] fp16
__device__ __align__(16) __half g_Wc2h[FF * FF];
__device__ __align__(16) float g_e1[SEG];
__device__ __align__(16) float g_e2[SEG];
__device__ __align__(16) int g_cnt[SEG];
__device__ __align__(16) int g_off[SEG];      // local (per-512-block) prescan; finalized via g_bsum
__device__ __align__(16) int g_bsum[1024];
__device__ __align__(16) int g_src_sorted[EE];

__device__ __forceinline__ void cpa16(void* dst_smem, const void* src) {
    uint32_t d = (uint32_t)__cvta_generic_to_shared(dst_smem);
    asm volatile("cp.async.cg.shared.global [%0], [%1], 16;" :: "r"(d), "l"(src));
}

// ---------------- K0: precompute v1,v2 and fp16 W^T per relation ----------------
__global__ void precompute_kernel(const float* __restrict__ W,
                                  const float* __restrict__ att1,
                                  const float* __restrict__ att2) {
    __shared__ float red1[128];
    __shared__ float red2[128];
    int rf = blockIdx.x;           // r*128 + f
    int r  = rf >> 7, f = rf & 127;
    int o  = threadIdx.x;
    float w = W[rf * 128 + o];
    g_Wh[(size_t)r * (FF * FF) + o * FF + f] = __float2half_rn(w);

    red1[o] = w * att1[o];
    red2[o] = w * att2[o];
    __syncthreads();
    for (int s = 64; s > 0; s >>= 1) {
        if (o < s) { red1[o] += red1[o + s]; red2[o] += red2[o + s]; }
        __syncthreads();
    }
    if (o == 0) { g_v1[rf] = red1[0]; g_v2[rf] = red2[0]; }
}

__global__ void wc_convert_kernel(const float* __restrict__ Wc) {
    int o = blockIdx.x, k = threadIdx.x;
    g_Wc1h[o * FF + k] = __float2half_rn(Wc[o * 256 + k]);
    g_Wc2h[o * FF + k] = __float2half_rn(Wc[o * 256 + 128 + k]);
}

// ---------------- convert node_h -> fp16 ----------------
__global__ void nodeh_convert_kernel(const float* __restrict__ node_h) {
    size_t i = (size_t)blockIdx.x * blockDim.x + threadIdx.x;   // one per 8 elems
    if (i >= (size_t)NN * FF / 8) return;
    const float4* p = reinterpret_cast<const float4*>(node_h) + i * 2;
    float4 a = p[0], b = p[1];
    __half2 h0 = __floats2half2_rn(a.x, a.y);
    __half2 h1 = __floats2half2_rn(a.z, a.w);
    __half2 h2 = __floats2half2_rn(b.x, b.y);
    __half2 h3 = __floats2half2_rn(b.z, b.w);
    uint4 o;
    o.x = *reinterpret_cast<uint32_t*>(&h0);
    o.y = *reinterpret_cast<uint32_t*>(&h1);
    o.z = *reinterpret_cast<uint32_t*>(&h2);
    o.w = *reinterpret_cast<uint32_t*>(&h3);
    reinterpret_cast<uint4*>(g_nodeH)[i] = o;
}

// ---------------- CSR build ----------------
// hist: 8 edges per thread for deep MLP on the index streams
__global__ void hist_kernel(const int4* __restrict__ edst4, const int4* __restrict__ erel4) {
    int i = blockIdx.x * blockDim.x + threadIdx.x;
    if (i >= EE / 8) return;
    int4 d0 = edst4[i * 2], d1 = edst4[i * 2 + 1];
    int4 r0 = erel4[i * 2], r1 = erel4[i * 2 + 1];
    atomicAdd(&g_cnt[r0.x * NN + d0.x], 1);
    atomicAdd(&g_cnt[r0.y * NN + d0.y], 1);
    atomicAdd(&g_cnt[r0.z * NN + d0.z], 1);
    atomicAdd(&g_cnt[r0.w * NN + d0.w], 1);
    atomicAdd(&g_cnt[r1.x * NN + d1.x], 1);
    atomicAdd(&g_cnt[r1.y * NN + d1.y], 1);
    atomicAdd(&g_cnt[r1.z * NN + d1.z], 1);
    atomicAdd(&g_cnt[r1.w * NN + d1.w], 1);
}

// scan1: per-512-block exclusive prescan via warp shuffles (2 syncs)
__global__ void scan1_kernel() {
    __shared__ int wsum[16];
    int tid = threadIdx.x;
    int idx = blockIdx.x * 512 + tid;
    int lane = tid & 31, wid = tid >> 5;
    int v = (idx < SEG) ? g_cnt[idx] : 0;
    int incl = v;
#pragma unroll
    for (int s = 1; s < 32; s <<= 1) {
        int u = __shfl_up_sync(0xffffffffu, incl, s);
        if (lane >= s) incl += u;
    }
    if (lane == 31) wsum[wid] = incl;
    __syncthreads();
    if (wid == 0) {
        int wv = (lane < 16) ? wsum[lane] : 0;
        int wi = wv;
#pragma unroll
        for (int s = 1; s < 16; s <<= 1) {
            int u = __shfl_up_sync(0xffffffffu, wi, s);
            if (lane >= s) wi += u;
        }
        if (lane < 16) wsum[lane] = wi - wv;   // exclusive
        if (lane == 15) g_bsum[blockIdx.x] = wi;  // block total
    }
    __syncthreads();
    if (idx < SEG) g_off[idx] = incl - v + wsum[wid];
}

// scan2: single block exclusive scan of block sums (<=1024) via shuffles
__global__ void scan2_kernel(int nblk) {
    __shared__ int wsum[32];
    int tid = threadIdx.x;
    int lane = tid & 31, wid = tid >> 5;
    int v = (tid < nblk) ? g_bsum[tid] : 0;
    int incl = v;
#pragma unroll
    for (int s = 1; s < 32; s <<= 1) {
        int u = __shfl_up_sync(0xffffffffu, incl, s);
        if (lane >= s) incl += u;
    }
    if (lane == 31) wsum[wid] = incl;
    __syncthreads();
    if (wid == 0) {
        int wv = wsum[lane];
        int wi = wv;
#pragma unroll
        for (int s = 1; s < 32; s <<= 1) {
            int u = __shfl_up_sync(0xffffffffu, wi, s);
            if (lane >= s) wi += u;
        }
        wsum[lane] = wi - wv;
    }
    __syncthreads();
    if (tid < nblk) g_bsum[tid] = incl - v + wsum[wid];
}

// permute: final position = local-prescan atomic + block base (folds old scan3)
__global__ void permute_kernel(const int4* __restrict__ esrc4,
                               const int4* __restrict__ edst4,
                               const int4* __restrict__ erel4) {
    int i = blockIdx.x * blockDim.x + threadIdx.x;
    if (i >= EE / 4) return;
    int4 s = esrc4[i];
    int4 d = edst4[i];
    int4 r = erel4[i];
    int k0 = r.x * NN + d.x;
    int k1 = r.y * NN + d.y;
    int k2 = r.z * NN + d.z;
    int k3 = r.w * NN + d.w;
    int p0 = atomicAdd(&g_off[k0], 1) + g_bsum[k0 >> 9];
    int p1 = atomicAdd(&g_off[k1], 1) + g_bsum[k1 >> 9];
    int p2 = atomicAdd(&g_off[k2], 1) + g_bsum[k2 >> 9];
    int p3 = atomicAdd(&g_off[k3], 1) + g_bsum[k3 >> 9];
    g_src_sorted[p0] = s.x;
    g_src_sorted[p1] = s.y;
    g_src_sorted[p2] = s.z;
    g_src_sorted[p3] = s.w;
}

// ---------------- gather: one warp per (rel,dst) segment; fp16 in, fp16 out ----------------
__global__ __launch_bounds__(256) void gather_kernel() {
    int seg = blockIdx.x * 8 + (threadIdx.x >> 5);
    if (seg >= SEG) return;
    int l = threadIdx.x & 31;
    int r = seg / NN;
    int deg = g_cnt[seg];
    // post-permute g_off[seg] = local_prescan + deg; global base = local + bsum
    int off = g_off[seg] + g_bsum[seg >> 9] - deg;

    const uint2* h2 = reinterpret_cast<const uint2*>(g_nodeH);
    float4 acc = make_float4(0.f, 0.f, 0.f, 0.f);
    int e = 0;
    for (; e + 4 <= deg; e += 4) {
        int i0 = g_src_sorted[off + e];
        int i1 = g_src_sorted[off + e + 1];
        int i2 = g_src_sorted[off + e + 2];
        int i3 = g_src_sorted[off + e + 3];
        uint2 u0 = h2[(size_t)i0 * 32 + l];
        uint2 u1 = h2[(size_t)i1 * 32 + l];
        uint2 u2 = h2[(size_t)i2 * 32 + l];
        uint2 u3 = h2[(size_t)i3 * 32 + l];
        float2 a0 = __half22float2(*reinterpret_cast<__half2*>(&u0.x));
        float2 a1 = __half22float2(*reinterpret_cast<__half2*>(&u0.y));
        float2 b0 = __half22float2(*reinterpret_cast<__half2*>(&u1.x));
        float2 b1 = __half22float2(*reinterpret_cast<__half2*>(&u1.y));
        float2 c0 = __half22float2(*reinterpret_cast<__half2*>(&u2.x));
        float2 c1 = __half22float2(*reinterpret_cast<__half2*>(&u2.y));
        float2 d0 = __half22float2(*reinterpret_cast<__half2*>(&u3.x));
        float2 d1 = __half22float2(*reinterpret_cast<__half2*>(&u3.y));
        acc.x += (a0.x + b0.x) + (c0.x + d0.x);
        acc.y += (a0.y + b0.y) + (c0.y + d0.y);
        acc.z += (a1.x + b1.x) + (c1.x + d1.x);
        acc.w += (a1.y + b1.y) + (c1.y + d1.y);
    }
    for (; e < deg; e++) {
        int i0 = g_src_sorted[off + e];
        uint2 ua = h2[(size_t)i0 * 32 + l];
        float2 a0 = __half22float2(*reinterpret_cast<__half2*>(&ua.x));
        float2 a1 = __half22float2(*reinterpret_cast<__half2*>(&ua.y));
        acc.x += a0.x; acc.y += a0.y; acc.z += a1.x; acc.w += a1.y;
    }

    __half2 h01 = __floats2half2_rn(acc.x, acc.y);
    __half2 h23 = __floats2half2_rn(acc.z, acc.w);
    uint2 packed;
    packed.x = *reinterpret_cast<uint32_t*>(&h01);
    packed.y = *reinterpret_cast<uint32_t*>(&h23);
    reinterpret_cast<uint2*>(g_aggH)[(size_t)seg * 32 + l] = packed;

    float4 w1 = reinterpret_cast<const float4*>(g_v1)[r * 32 + l];
    float4 w2 = reinterpret_cast<const float4*>(g_v2)[r * 32 + l];
    float p1 = acc.x * w1.x + acc.y * w1.y + acc.z * w1.z + acc.w * w1.w;
    float p2 = acc.x * w2.x + acc.y * w2.y + acc.z * w2.z + acc.w * w2.w;
#pragma unroll
    for (int s = 16; s > 0; s >>= 1) {
        p1 += __shfl_xor_sync(0xffffffffu, p1, s);
        p2 += __shfl_xor_sync(0xffffffffu, p2, s);
    }
    if (l == 0) { g_e1[seg] = p1; g_e2[seg] = p2; }
}

// ---------------- K4: fused softmax + factored GEMM (2 blocks/SM) ----------------
__device__ __forceinline__ void mma16(float d[4], uint32_t a0, uint32_t a1, uint32_t a2, uint32_t a3,
                                      uint32_t b0, uint32_t b1) {
    asm volatile(
        "mma.sync.aligned.m16n8k16.row.col.f32.f16.f16.f32 "
        "{%0,%1,%2,%3},{%4,%5,%6,%7},{%8,%9},{%0,%1,%2,%3};"
        : "+f"(d[0]), "+f"(d[1]), "+f"(d[2]), "+f"(d[3])
        : "r"(a0), "r"(a1), "r"(a2), "r"(a3), "r"(b0), "r"(b1));
}

#define STR 136
#define AH_OFF 0                         // [2][64][STR] halves; Y/Z alias this after stage 1
#define BW_OFF (2 * 64 * STR)            // [128][STR] single-buffered W
#define WC2_OFF (BW_OFF + 128 * STR)     // [128][STR]
#define CS_OFF (WC2_OFF + 128 * STR)     // float c1s[384], c2s[384]
#define GEMM_SMEM (CS_OFF * 2 + 768 * 4) // 107520 bytes

__global__ __launch_bounds__(256, 2) void gemm_kernel(float* __restrict__ out,
                                                      const float* __restrict__ bc) {
    extern __shared__ __half sh[];
    __half* Ah   = sh + AH_OFF;
    __half* Bw   = sh + BW_OFF;
    __half* Wc2s = sh + WC2_OFF;
    float* c1s = reinterpret_cast<float*>(sh + CS_OFF);
    float* c2s = c1s + 384;

    int n0 = blockIdx.x * 64;
    int t = threadIdx.x;
    int warp = t >> 5, lane = t & 31;
    int wm = warp >> 2, wn = warp & 3;   // 2x4 warps, warp tile 32 rows x 32 cols
    int g = lane >> 2, tg = lane & 3;
    int rowa = wm * 32 + g;

    auto ldA = [&](int s, int buf) {
#pragma unroll
        for (int j = 0; j < 4; j++) {
            int lin = t + 256 * j;
            int row = lin >> 4;
            int c8 = (lin & 15) * 8;
            int n = n0 + row;
            if (n >= NN) n = 0;
            cpa16(Ah + buf * 64 * STR + row * STR + c8,
                  g_aggH + ((size_t)s * NN + n) * FF + c8);
        }
    };
    auto ldW = [&](__half* dst, const __half* src) {
#pragma unroll
        for (int j = 0; j < 8; j++) {
            int lin = t + 256 * j;
            int o = lin >> 4;
            int c8 = (lin & 15) * 8;
            cpa16(dst + o * STR + c8, src + o * FF + c8);
        }
    };

    // prologue: G0 = {A0, W0}, G1 = {A1}
    ldA(0, 0); ldW(Bw, g_Wh);
    asm volatile("cp.async.commit_group;" ::: "memory");
    ldA(1, 1);
    asm volatile("cp.async.commit_group;" ::: "memory");

    // fused softmax: threads 0..63, one node each
    if (t < 64) {
        int n = n0 + t;
        if (n < NN) {
            float e1[RR], e2[RR], dg[RR];
#pragma unroll
            for (int r = 0; r < RR; r++) {
                dg[r] = 1.0f + (float)g_cnt[r * NN + n];
                e1[r] = g_e1[r * NN + n] / dg[r];
                e2[r] = g_e2[r * NN + n] / dg[r];
            }
            float m1 = e1[0], m2 = e2[0];
#pragma unroll
            for (int r = 1; r < RR; r++) { m1 = fmaxf(m1, e1[r]); m2 = fmaxf(m2, e2[r]); }
            float s1 = 0.f, s2 = 0.f;
#pragma unroll
            for (int r = 0; r < RR; r++) {
                e1[r] = __expf(e1[r] - m1); s1 += e1[r];
                e2[r] = __expf(e2[r] - m2); s2 += e2[r];
            }
            float i1 = 1.0f / s1, i2 = 1.0f / s2;
#pragma unroll
            for (int r = 0; r < RR; r++) {
                c1s[t * 6 + r] = e1[r] * i1 / dg[r];
                c2s[t * 6 + r] = e2[r] * i2 / dg[r];
            }
        } else {
#pragma unroll
            for (int r = 0; r < RR; r++) { c1s[t * 6 + r] = 0.f; c2s[t * 6 + r] = 0.f; }
        }
    }

    float P[2][4][4], Y[2][4][4], Z[2][4][4];
#pragma unroll
    for (int mi = 0; mi < 2; mi++)
#pragma unroll
        for (int ni = 0; ni < 4; ni++)
#pragma unroll
            for (int j = 0; j < 4; j++) { P[mi][ni][j] = 0.f; Y[mi][ni][j] = 0.f; Z[mi][ni][j] = 0.f; }

    auto mmastep = [&](const __half* Abase, const __half* Bbase) {
#pragma unroll
        for (int ks = 0; ks < 8; ks++) {
            int k0 = ks * 16;
            uint32_t a[2][4];
#pragma unroll
            for (int mi = 0; mi < 2; mi++) {
                const __half* ap = Abase + (rowa + mi * 16) * STR + k0 + tg * 2;
                a[mi][0] = *reinterpret_cast<const uint32_t*>(ap);
                a[mi][1] = *reinterpret_cast<const uint32_t*>(ap + 8 * STR);
                a[mi][2] = *reinterpret_cast<const uint32_t*>(ap + 8);
                a[mi][3] = *reinterpret_cast<const uint32_t*>(ap + 8 * STR + 8);
            }
            uint32_t b[4][2];
#pragma unroll
            for (int ni = 0; ni < 4; ni++) {
                const __half* bp = Bbase + (wn * 32 + ni * 8 + g) * STR + k0 + tg * 2;
                b[ni][0] = *reinterpret_cast<const uint32_t*>(bp);
                b[ni][1] = *reinterpret_cast<const uint32_t*>(bp + 8);
            }
#pragma unroll
            for (int mi = 0; mi < 2; mi++)
#pragma unroll
                for (int ni = 0; ni < 4; ni++)
                    mma16(P[mi][ni], a[mi][0], a[mi][1], a[mi][2], a[mi][3],
                          b[ni][0], b[ni][1]);
        }
    };

    for (int s = 0; s < 6; s++) {
        if (s == 5) { asm volatile("cp.async.wait_group 0;" ::: "memory"); }
        else        { asm volatile("cp.async.wait_group 1;" ::: "memory"); }
        __syncthreads();
        mmastep(Ah + (s & 1) * 64 * STR, Bw);
        if (s < 5) {
            __syncthreads();
            ldW(Bw, g_Wh + (size_t)(s + 1) * (FF * FF));
            asm volatile("cp.async.commit_group;" ::: "memory");
            if (s + 2 < 6) {
                ldA(s + 2, s & 1);
                asm volatile("cp.async.commit_group;" ::: "memory");
            }
        }
#pragma unroll
        for (int mi = 0; mi < 2; mi++) {
            int rl = rowa + mi * 16;
            float c1a = c1s[rl * 6 + s];
            float c1b = c1s[(rl + 8) * 6 + s];
            float c2a = c2s[rl * 6 + s];
            float c2b = c2s[(rl + 8) * 6 + s];
#pragma unroll
            for (int ni = 0; ni < 4; ni++) {
                Y[mi][ni][0] += c1a * P[mi][ni][0];
                Y[mi][ni][1] += c1a * P[mi][ni][1];
                Y[mi][ni][2] += c1b * P[mi][ni][2];
                Y[mi][ni][3] += c1b * P[mi][ni][3];
                Z[mi][ni][0] += c2a * P[mi][ni][0];
                Z[mi][ni][1] += c2a * P[mi][ni][1];
                Z[mi][ni][2] += c2b * P[mi][ni][2];
                Z[mi][ni][3] += c2b * P[mi][ni][3];
                P[mi][ni][0] = 0.f; P[mi][ni][1] = 0.f;
                P[mi][ni][2] = 0.f; P[mi][ni][3] = 0.f;
            }
        }
    }

    __syncthreads();
    ldW(Bw, g_Wc1h);
    ldW(Wc2s, g_Wc2h);
    asm volatile("cp.async.commit_group;" ::: "memory");

    __half* Yt = Ah;
    __half* Zt = Ah + 64 * STR;
#pragma unroll
    for (int mi = 0; mi < 2; mi++) {
        int row = rowa + mi * 16;
#pragma unroll
        for (int ni = 0; ni < 4; ni++) {
            int col = wn * 32 + ni * 8 + tg * 2;
            *reinterpret_cast<__half2*>(Yt + row * STR + col) =
                __floats2half2_rn(Y[mi][ni][0], Y[mi][ni][1]);
            *reinterpret_cast<__half2*>(Yt + (row + 8) * STR + col) =
                __floats2half2_rn(Y[mi][ni][2], Y[mi][ni][3]);
            *reinterpret_cast<__half2*>(Zt + row * STR + col) =
                __floats2half2_rn(Z[mi][ni][0], Z[mi][ni][1]);
            *reinterpret_cast<__half2*>(Zt + (row + 8) * STR + col) =
                __floats2half2_rn(Z[mi][ni][2], Z[mi][ni][3]);
        }
    }
    asm volatile("cp.async.wait_group 0;" ::: "memory");
    __syncthreads();

    mmastep(Yt, Bw);
    mmastep(Zt, Wc2s);

#pragma unroll
    for (int mi = 0; mi < 2; mi++) {
        int ra = n0 + rowa + mi * 16;
#pragma unroll
        for (int ni = 0; ni < 4; ni++) {
            int col = wn * 32 + ni * 8 + tg * 2;
            float b0 = 6.0f * bc[col];
            float b1 = 6.0f * bc[col + 1];
            if (ra < NN) {
                float2 v = make_float2(P[mi][ni][0] + b0, P[mi][ni][1] + b1);
                *reinterpret_cast<float2*>(&out[(size_t)ra * FF + col]) = v;
            }
            if (ra + 8 < NN) {
                float2 v = make_float2(P[mi][ni][2] + b0, P[mi][ni][3] + b1);
                *reinterpret_cast<float2*>(&out[(size_t)(ra + 8) * FF + col]) = v;
            }
        }
    }
}

// ---------------- launch ----------------
extern "C" void kernel_launch(void* const* d_in, const int* in_sizes, int n_in,
                              void* d_out, int out_size) {
    const float* node_h = (const float*)d_in[0];
    const float* W      = (const float*)d_in[1];
    const float* att1   = (const float*)d_in[2];
    const float* att2   = (const float*)d_in[3];
    const float* Wc     = (const float*)d_in[4];
    const float* bc     = (const float*)d_in[5];
    const int*   esrc   = (const int*)d_in[6];
    const int*   edst   = (const int*)d_in[7];
    const int*   erel   = (const int*)d_in[8];
    float* out = (float*)d_out;

    static int inited = 0;
    static cudaStream_t s1;
    static cudaEvent_t evFork, evPre;
    static void* cntAddr = nullptr;
    if (!inited) {
        cudaFuncSetAttribute(gemm_kernel, cudaFuncAttributeMaxDynamicSharedMemorySize, GEMM_SMEM);
        cudaStreamCreateWithFlags(&s1, cudaStreamNonBlocking);
        cudaEventCreateWithFlags(&evFork, cudaEventDisableTiming);
        cudaEventCreateWithFlags(&evPre, cudaEventDisableTiming);
        cudaGetSymbolAddress(&cntAddr, g_cnt);
        inited = 1;
    }

    const int nblk1 = (SEG + 511) / 512;   // 586

    // fork: precompute branch on s1 (independent of CSR build)
    cudaEventRecord(evFork, 0);
    cudaStreamWaitEvent(s1, evFork, 0);
    if (out_size >= NN * FF + RR * FF * FF) {
        cudaMemcpyAsync(out + (size_t)NN * FF, W,
                        sizeof(float) * RR * FF * FF, cudaMemcpyDeviceToDevice, s1);
    }
    precompute_kernel<<<RR * FF, 128, 0, s1>>>(W, att1, att2);
    nodeh_convert_kernel<<<(NN * FF / 8 + 255) / 256, 256, 0, s1>>>(node_h);
    wc_convert_kernel<<<FF, 128, 0, s1>>>(Wc);
    cudaEventRecord(evPre, s1);

    // CSR branch on stream 0
    cudaMemsetAsync(cntAddr, 0, SEG * sizeof(int), 0);
    hist_kernel<<<(EE / 8 + 255) / 256, 256>>>((const int4*)edst, (const int4*)erel);
    scan1_kernel<<<nblk1, 512>>>();
    scan2_kernel<<<1, 1024>>>(nblk1);
    permute_kernel<<<(EE / 4 + 255) / 256, 256>>>((const int4*)esrc, (const int4*)edst,
                                                  (const int4*)erel);

    // join precompute before gather
    cudaStreamWaitEvent(0, evPre, 0);

    gather_kernel<<<(SEG + 7) / 8, 256>>>();
    gemm_kernel<<<(NN + 63) / 64, 256, GEMM_SMEM>>>(out, bc);
}

// round 13
// speedup vs baseline: 1.2038x; 1.0236x over previous
#include <cuda_runtime.h>
#include <cuda_fp16.h>
#include <cstdint>

#define NN 50000
#define EE 800000
#define RR 6
#define FF 128
#define SEG (RR * NN)

// ---------------- scratch (static device globals; no allocations) ----------------
__device__ __align__(16) __half g_nodeH[(size_t)NN * FF];  // 12.8 MB fp16 node_h
__device__ __align__(16) __half g_aggH[(size_t)SEG * FF];  // 76.8 MB fp16 agg
__device__ __align__(16) float g_v1[RR * FF];
__device__ __align__(16) float g_v2[RR * FF];
__device__ __align__(16) __half g_Wh[RR * FF * FF];        // [r][o][f] = W[r][f][o] fp16
__device__ __align__(16) __half g_Wc1h[FF * FF];           // [o][k] fp16
__device__ __align__(16) __half g_Wc2h[FF * FF];
__device__ __align__(16) float g_e1[SEG];
__device__ __align__(16) float g_e2[SEG];
__device__ __align__(16) int g_cnt[SEG];                   // zero-init; invariant: all-zero at launch end
__device__ __align__(16) int g_off[SEG];                   // local (per-512-block) prescan
__device__ __align__(16) int g_bsum[1024];
__device__ __align__(16) int g_src_sorted[EE];

__device__ __forceinline__ void cpa16(void* dst_smem, const void* src) {
    uint32_t d = (uint32_t)__cvta_generic_to_shared(dst_smem);
    asm volatile("cp.async.cg.shared.global [%0], [%1], 16;" :: "r"(d), "l"(src));
}

// ---------------- K0: precompute v1,v2, fp16 W^T, and Wc convert (blocks >= 768) ----------------
__global__ void precompute_kernel(const float* __restrict__ W,
                                  const float* __restrict__ att1,
                                  const float* __restrict__ att2,
                                  const float* __restrict__ Wc) {
    if (blockIdx.x >= RR * FF) {
        int o = blockIdx.x - RR * FF;      // 0..127
        int k = threadIdx.x;
        g_Wc1h[o * FF + k] = __float2half_rn(Wc[o * 256 + k]);
        g_Wc2h[o * FF + k] = __float2half_rn(Wc[o * 256 + 128 + k]);
        return;
    }
    __shared__ float red1[128];
    __shared__ float red2[128];
    int rf = blockIdx.x;           // r*128 + f
    int r  = rf >> 7, f = rf & 127;
    int o  = threadIdx.x;
    float w = W[rf * 128 + o];
    g_Wh[(size_t)r * (FF * FF) + o * FF + f] = __float2half_rn(w);

    red1[o] = w * att1[o];
    red2[o] = w * att2[o];
    __syncthreads();
    for (int s = 64; s > 0; s >>= 1) {
        if (o < s) { red1[o] += red1[o + s]; red2[o] += red2[o + s]; }
        __syncthreads();
    }
    if (o == 0) { g_v1[rf] = red1[0]; g_v2[rf] = red2[0]; }
}

// ---------------- convert node_h -> fp16 ----------------
__global__ void nodeh_convert_kernel(const float* __restrict__ node_h) {
    size_t i = (size_t)blockIdx.x * blockDim.x + threadIdx.x;   // one per 8 elems
    if (i >= (size_t)NN * FF / 8) return;
    const float4* p = reinterpret_cast<const float4*>(node_h) + i * 2;
    float4 a = p[0], b = p[1];
    __half2 h0 = __floats2half2_rn(a.x, a.y);
    __half2 h1 = __floats2half2_rn(a.z, a.w);
    __half2 h2 = __floats2half2_rn(b.x, b.y);
    __half2 h3 = __floats2half2_rn(b.z, b.w);
    uint4 o;
    o.x = *reinterpret_cast<uint32_t*>(&h0);
    o.y = *reinterpret_cast<uint32_t*>(&h1);
    o.z = *reinterpret_cast<uint32_t*>(&h2);
    o.w = *reinterpret_cast<uint32_t*>(&h3);
    reinterpret_cast<uint4*>(g_nodeH)[i] = o;
}

// ---------------- CSR build ----------------
__global__ void hist_kernel(const int4* __restrict__ edst4, const int4* __restrict__ erel4) {
    int i = blockIdx.x * blockDim.x + threadIdx.x;
    if (i >= EE / 8) return;
    int4 d0 = edst4[i * 2], d1 = edst4[i * 2 + 1];
    int4 r0 = erel4[i * 2], r1 = erel4[i * 2 + 1];
    atomicAdd(&g_cnt[r0.x * NN + d0.x], 1);
    atomicAdd(&g_cnt[r0.y * NN + d0.y], 1);
    atomicAdd(&g_cnt[r0.z * NN + d0.z], 1);
    atomicAdd(&g_cnt[r0.w * NN + d0.w], 1);
    atomicAdd(&g_cnt[r1.x * NN + d1.x], 1);
    atomicAdd(&g_cnt[r1.y * NN + d1.y], 1);
    atomicAdd(&g_cnt[r1.z * NN + d1.z], 1);
    atomicAdd(&g_cnt[r1.w * NN + d1.w], 1);
}

// scan1: per-512-block exclusive prescan via warp shuffles
__global__ void scan1_kernel() {
    __shared__ int wsum[16];
    int tid = threadIdx.x;
    int idx = blockIdx.x * 512 + tid;
    int lane = tid & 31, wid = tid >> 5;
    int v = (idx < SEG) ? g_cnt[idx] : 0;
    int incl = v;
#pragma unroll
    for (int s = 1; s < 32; s <<= 1) {
        int u = __shfl_up_sync(0xffffffffu, incl, s);
        if (lane >= s) incl += u;
    }
    if (lane == 31) wsum[wid] = incl;
    __syncthreads();
    if (wid == 0) {
        int wv = (lane < 16) ? wsum[lane] : 0;
        int wi = wv;
#pragma unroll
        for (int s = 1; s < 16; s <<= 1) {
            int u = __shfl_up_sync(0xffffffffu, wi, s);
            if (lane >= s) wi += u;
        }
        if (lane < 16) wsum[lane] = wi - wv;
        if (lane == 15) g_bsum[blockIdx.x] = wi;
    }
    __syncthreads();
    if (idx < SEG) g_off[idx] = incl - v + wsum[wid];
}

// scan2: single block exclusive scan of block sums
__global__ void scan2_kernel(int nblk) {
    __shared__ int wsum[32];
    int tid = threadIdx.x;
    int lane = tid & 31, wid = tid >> 5;
    int v = (tid < nblk) ? g_bsum[tid] : 0;
    int incl = v;
#pragma unroll
    for (int s = 1; s < 32; s <<= 1) {
        int u = __shfl_up_sync(0xffffffffu, incl, s);
        if (lane >= s) incl += u;
    }
    if (lane == 31) wsum[wid] = incl;
    __syncthreads();
    if (wid == 0) {
        int wv = wsum[lane];
        int wi = wv;
#pragma unroll
        for (int s = 1; s < 32; s <<= 1) {
            int u = __shfl_up_sync(0xffffffffu, wi, s);
            if (lane >= s) wi += u;
        }
        wsum[lane] = wi - wv;
    }
    __syncthreads();
    if (tid < nblk) g_bsum[tid] = incl - v + wsum[wid];
}

// permute: final position = local-prescan atomic + block base
__global__ void permute_kernel(const int4* __restrict__ esrc4,
                               const int4* __restrict__ edst4,
                               const int4* __restrict__ erel4) {
    int i = blockIdx.x * blockDim.x + threadIdx.x;
    if (i >= EE / 4) return;
    int4 s = esrc4[i];
    int4 d = edst4[i];
    int4 r = erel4[i];
    int k0 = r.x * NN + d.x;
    int k1 = r.y * NN + d.y;
    int k2 = r.z * NN + d.z;
    int k3 = r.w * NN + d.w;
    int p0 = atomicAdd(&g_off[k0], 1) + g_bsum[k0 >> 9];
    int p1 = atomicAdd(&g_off[k1], 1) + g_bsum[k1 >> 9];
    int p2 = atomicAdd(&g_off[k2], 1) + g_bsum[k2 >> 9];
    int p3 = atomicAdd(&g_off[k3], 1) + g_bsum[k3 >> 9];
    asm volatile("st.global.cs.u32 [%0], %1;" :: "l"(g_src_sorted + p0), "r"(s.x) : "memory");
    asm volatile("st.global.cs.u32 [%0], %1;" :: "l"(g_src_sorted + p1), "r"(s.y) : "memory");
    asm volatile("st.global.cs.u32 [%0], %1;" :: "l"(g_src_sorted + p2), "r"(s.z) : "memory");
    asm volatile("st.global.cs.u32 [%0], %1;" :: "l"(g_src_sorted + p3), "r"(s.w) : "memory");
}

// ---------------- gather: one warp per (rel,dst) segment; fp16 in, fp16 out ----------------
__global__ __launch_bounds__(256) void gather_kernel() {
    int seg = blockIdx.x * 8 + (threadIdx.x >> 5);
    if (seg >= SEG) return;
    int l = threadIdx.x & 31;
    int r = seg / NN;
    int deg = g_cnt[seg];
    int off = g_off[seg] + g_bsum[seg >> 9] - deg;   // post-permute base

    const uint2* h2 = reinterpret_cast<const uint2*>(g_nodeH);
    float4 acc = make_float4(0.f, 0.f, 0.f, 0.f);
    int e = 0;
    for (; e + 4 <= deg; e += 4) {
        int i0 = g_src_sorted[off + e];
        int i1 = g_src_sorted[off + e + 1];
        int i2 = g_src_sorted[off + e + 2];
        int i3 = g_src_sorted[off + e + 3];
        uint2 u0 = h2[(size_t)i0 * 32 + l];
        uint2 u1 = h2[(size_t)i1 * 32 + l];
        uint2 u2 = h2[(size_t)i2 * 32 + l];
        uint2 u3 = h2[(size_t)i3 * 32 + l];
        float2 a0 = __half22float2(*reinterpret_cast<__half2*>(&u0.x));
        float2 a1 = __half22float2(*reinterpret_cast<__half2*>(&u0.y));
        float2 b0 = __half22float2(*reinterpret_cast<__half2*>(&u1.x));
        float2 b1 = __half22float2(*reinterpret_cast<__half2*>(&u1.y));
        float2 c0 = __half22float2(*reinterpret_cast<__half2*>(&u2.x));
        float2 c1 = __half22float2(*reinterpret_cast<__half2*>(&u2.y));
        float2 d0 = __half22float2(*reinterpret_cast<__half2*>(&u3.x));
        float2 d1 = __half22float2(*reinterpret_cast<__half2*>(&u3.y));
        acc.x += (a0.x + b0.x) + (c0.x + d0.x);
        acc.y += (a0.y + b0.y) + (c0.y + d0.y);
        acc.z += (a1.x + b1.x) + (c1.x + d1.x);
        acc.w += (a1.y + b1.y) + (c1.y + d1.y);
    }
    for (; e < deg; e++) {
        int i0 = g_src_sorted[off + e];
        uint2 ua = h2[(size_t)i0 * 32 + l];
        float2 a0 = __half22float2(*reinterpret_cast<__half2*>(&ua.x));
        float2 a1 = __half22float2(*reinterpret_cast<__half2*>(&ua.y));
        acc.x += a0.x; acc.y += a0.y; acc.z += a1.x; acc.w += a1.y;
    }

    __half2 h01 = __floats2half2_rn(acc.x, acc.y);
    __half2 h23 = __floats2half2_rn(acc.z, acc.w);
    uint32_t px = *reinterpret_cast<uint32_t*>(&h01);
    uint32_t py = *reinterpret_cast<uint32_t*>(&h23);
    // evict-first streaming store: keep node_h resident in L2
    asm volatile("st.global.cs.v2.u32 [%0], {%1,%2};"
                 :: "l"(reinterpret_cast<uint2*>(g_aggH) + (size_t)seg * 32 + l),
                    "r"(px), "r"(py) : "memory");

    float4 w1 = reinterpret_cast<const float4*>(g_v1)[r * 32 + l];
    float4 w2 = reinterpret_cast<const float4*>(g_v2)[r * 32 + l];
    float p1 = acc.x * w1.x + acc.y * w1.y + acc.z * w1.z + acc.w * w1.w;
    float p2 = acc.x * w2.x + acc.y * w2.y + acc.z * w2.z + acc.w * w2.w;
#pragma unroll
    for (int s = 16; s > 0; s >>= 1) {
        p1 += __shfl_xor_sync(0xffffffffu, p1, s);
        p2 += __shfl_xor_sync(0xffffffffu, p2, s);
    }
    if (l == 0) { g_e1[seg] = p1; g_e2[seg] = p2; }
}

// ---------------- K4: fused softmax + factored GEMM (2 blocks/SM) ----------------
__device__ __forceinline__ void mma16(float d[4], uint32_t a0, uint32_t a1, uint32_t a2, uint32_t a3,
                                      uint32_t b0, uint32_t b1) {
    asm volatile(
        "mma.sync.aligned.m16n8k16.row.col.f32.f16.f16.f32 "
        "{%0,%1,%2,%3},{%4,%5,%6,%7},{%8,%9},{%0,%1,%2,%3};"
        : "+f"(d[0]), "+f"(d[1]), "+f"(d[2]), "+f"(d[3])
        : "r"(a0), "r"(a1), "r"(a2), "r"(a3), "r"(b0), "r"(b1));
}

#define STR 136
#define AH_OFF 0
#define BW_OFF (2 * 64 * STR)
#define WC2_OFF (BW_OFF + 128 * STR)
#define CS_OFF (WC2_OFF + 128 * STR)
#define GEMM_SMEM (CS_OFF * 2 + 768 * 4) // 107520 bytes

__global__ __launch_bounds__(256, 2) void gemm_kernel(float* __restrict__ out,
                                                      const float* __restrict__ bc) {
    extern __shared__ __half sh[];
    __half* Ah   = sh + AH_OFF;
    __half* Bw   = sh + BW_OFF;
    __half* Wc2s = sh + WC2_OFF;
    float* c1s = reinterpret_cast<float*>(sh + CS_OFF);
    float* c2s = c1s + 384;

    int n0 = blockIdx.x * 64;
    int t = threadIdx.x;
    int warp = t >> 5, lane = t & 31;
    int wm = warp >> 2, wn = warp & 3;
    int g = lane >> 2, tg = lane & 3;
    int rowa = wm * 32 + g;

    auto ldA = [&](int s, int buf) {
#pragma unroll
        for (int j = 0; j < 4; j++) {
            int lin = t + 256 * j;
            int row = lin >> 4;
            int c8 = (lin & 15) * 8;
            int n = n0 + row;
            if (n >= NN) n = 0;
            cpa16(Ah + buf * 64 * STR + row * STR + c8,
                  g_aggH + ((size_t)s * NN + n) * FF + c8);
        }
    };
    auto ldW = [&](__half* dst, const __half* src) {
#pragma unroll
        for (int j = 0; j < 8; j++) {
            int lin = t + 256 * j;
            int o = lin >> 4;
            int c8 = (lin & 15) * 8;
            cpa16(dst + o * STR + c8, src + o * FF + c8);
        }
    };

    // prologue: G0 = {A0, W0}, G1 = {A1}
    ldA(0, 0); ldW(Bw, g_Wh);
    asm volatile("cp.async.commit_group;" ::: "memory");
    ldA(1, 1);
    asm volatile("cp.async.commit_group;" ::: "memory");

    // fused softmax: threads 0..63, one node each; zero g_cnt afterwards
    // (restores the all-zero invariant so next launch's hist needs no memset)
    if (t < 64) {
        int n = n0 + t;
        if (n < NN) {
            float e1[RR], e2[RR], dg[RR];
#pragma unroll
            for (int r = 0; r < RR; r++) {
                dg[r] = 1.0f + (float)g_cnt[r * NN + n];
                e1[r] = g_e1[r * NN + n] / dg[r];
                e2[r] = g_e2[r * NN + n] / dg[r];
            }
#pragma unroll
            for (int r = 0; r < RR; r++) g_cnt[r * NN + n] = 0;
            float m1 = e1[0], m2 = e2[0];
#pragma unroll
            for (int r = 1; r < RR; r++) { m1 = fmaxf(m1, e1[r]); m2 = fmaxf(m2, e2[r]); }
            float s1 = 0.f, s2 = 0.f;
#pragma unroll
            for (int r = 0; r < RR; r++) {
                e1[r] = __expf(e1[r] - m1); s1 += e1[r];
                e2[r] = __expf(e2[r] - m2); s2 += e2[r];
            }
            float i1 = 1.0f / s1, i2 = 1.0f / s2;
#pragma unroll
            for (int r = 0; r < RR; r++) {
                c1s[t * 6 + r] = e1[r] * i1 / dg[r];
                c2s[t * 6 + r] = e2[r] * i2 / dg[r];
            }
        } else {
#pragma unroll
            for (int r = 0; r < RR; r++) { c1s[t * 6 + r] = 0.f; c2s[t * 6 + r] = 0.f; }
        }
    }

    float P[2][4][4], Y[2][4][4], Z[2][4][4];
#pragma unroll
    for (int mi = 0; mi < 2; mi++)
#pragma unroll
        for (int ni = 0; ni < 4; ni++)
#pragma unroll
            for (int j = 0; j < 4; j++) { P[mi][ni][j] = 0.f; Y[mi][ni][j] = 0.f; Z[mi][ni][j] = 0.f; }

    auto mmastep = [&](const __half* Abase, const __half* Bbase) {
#pragma unroll
        for (int ks = 0; ks < 8; ks++) {
            int k0 = ks * 16;
            uint32_t a[2][4];
#pragma unroll
            for (int mi = 0; mi < 2; mi++) {
                const __half* ap = Abase + (rowa + mi * 16) * STR + k0 + tg * 2;
                a[mi][0] = *reinterpret_cast<const uint32_t*>(ap);
                a[mi][1] = *reinterpret_cast<const uint32_t*>(ap + 8 * STR);
                a[mi][2] = *reinterpret_cast<const uint32_t*>(ap + 8);
                a[mi][3] = *reinterpret_cast<const uint32_t*>(ap + 8 * STR + 8);
            }
            uint32_t b[4][2];
#pragma unroll
            for (int ni = 0; ni < 4; ni++) {
                const __half* bp = Bbase + (wn * 32 + ni * 8 + g) * STR + k0 + tg * 2;
                b[ni][0] = *reinterpret_cast<const uint32_t*>(bp);
                b[ni][1] = *reinterpret_cast<const uint32_t*>(bp + 8);
            }
#pragma unroll
            for (int mi = 0; mi < 2; mi++)
#pragma unroll
                for (int ni = 0; ni < 4; ni++)
                    mma16(P[mi][ni], a[mi][0], a[mi][1], a[mi][2], a[mi][3],
                          b[ni][0], b[ni][1]);
        }
    };

    for (int s = 0; s < 6; s++) {
        if (s == 5) { asm volatile("cp.async.wait_group 0;" ::: "memory"); }
        else        { asm volatile("cp.async.wait_group 1;" ::: "memory"); }
        __syncthreads();
        mmastep(Ah + (s & 1) * 64 * STR, Bw);
        if (s < 5) {
            __syncthreads();
            ldW(Bw, g_Wh + (size_t)(s + 1) * (FF * FF));
            asm volatile("cp.async.commit_group;" ::: "memory");
            if (s + 2 < 6) {
                ldA(s + 2, s & 1);
                asm volatile("cp.async.commit_group;" ::: "memory");
            }
        }
#pragma unroll
        for (int mi = 0; mi < 2; mi++) {
            int rl = rowa + mi * 16;
            float c1a = c1s[rl * 6 + s];
            float c1b = c1s[(rl + 8) * 6 + s];
            float c2a = c2s[rl * 6 + s];
            float c2b = c2s[(rl + 8) * 6 + s];
#pragma unroll
            for (int ni = 0; ni < 4; ni++) {
                Y[mi][ni][0] += c1a * P[mi][ni][0];
                Y[mi][ni][1] += c1a * P[mi][ni][1];
                Y[mi][ni][2] += c1b * P[mi][ni][2];
                Y[mi][ni][3] += c1b * P[mi][ni][3];
                Z[mi][ni][0] += c2a * P[mi][ni][0];
                Z[mi][ni][1] += c2a * P[mi][ni][1];
                Z[mi][ni][2] += c2b * P[mi][ni][2];
                Z[mi][ni][3] += c2b * P[mi][ni][3];
                P[mi][ni][0] = 0.f; P[mi][ni][1] = 0.f;
                P[mi][ni][2] = 0.f; P[mi][ni][3] = 0.f;
            }
        }
    }

    __syncthreads();
    ldW(Bw, g_Wc1h);
    ldW(Wc2s, g_Wc2h);
    asm volatile("cp.async.commit_group;" ::: "memory");

    __half* Yt = Ah;
    __half* Zt = Ah + 64 * STR;
#pragma unroll
    for (int mi = 0; mi < 2; mi++) {
        int row = rowa + mi * 16;
#pragma unroll
        for (int ni = 0; ni < 4; ni++) {
            int col = wn * 32 + ni * 8 + tg * 2;
            *reinterpret_cast<__half2*>(Yt + row * STR + col) =
                __floats2half2_rn(Y[mi][ni][0], Y[mi][ni][1]);
            *reinterpret_cast<__half2*>(Yt + (row + 8) * STR + col) =
                __floats2half2_rn(Y[mi][ni][2], Y[mi][ni][3]);
            *reinterpret_cast<__half2*>(Zt + row * STR + col) =
                __floats2half2_rn(Z[mi][ni][0], Z[mi][ni][1]);
            *reinterpret_cast<__half2*>(Zt + (row + 8) * STR + col) =
                __floats2half2_rn(Z[mi][ni][2], Z[mi][ni][3]);
        }
    }
    asm volatile("cp.async.wait_group 0;" ::: "memory");
    __syncthreads();

    mmastep(Yt, Bw);
    mmastep(Zt, Wc2s);

#pragma unroll
    for (int mi = 0; mi < 2; mi++) {
        int ra = n0 + rowa + mi * 16;
#pragma unroll
        for (int ni = 0; ni < 4; ni++) {
            int col = wn * 32 + ni * 8 + tg * 2;
            float b0 = 6.0f * bc[col];
            float b1 = 6.0f * bc[col + 1];
            if (ra < NN) {
                float2 v = make_float2(P[mi][ni][0] + b0, P[mi][ni][1] + b1);
                *reinterpret_cast<float2*>(&out[(size_t)ra * FF + col]) = v;
            }
            if (ra + 8 < NN) {
                float2 v = make_float2(P[mi][ni][2] + b0, P[mi][ni][3] + b1);
                *reinterpret_cast<float2*>(&out[(size_t)(ra + 8) * FF + col]) = v;
            }
        }
    }
}

// ---------------- launch ----------------
extern "C" void kernel_launch(void* const* d_in, const int* in_sizes, int n_in,
                              void* d_out, int out_size) {
    const float* node_h = (const float*)d_in[0];
    const float* W      = (const float*)d_in[1];
    const float* att1   = (const float*)d_in[2];
    const float* att2   = (const float*)d_in[3];
    const float* Wc     = (const float*)d_in[4];
    const float* bc     = (const float*)d_in[5];
    const int*   esrc   = (const int*)d_in[6];
    const int*   edst   = (const int*)d_in[7];
    const int*   erel   = (const int*)d_in[8];
    float* out = (float*)d_out;

    static int inited = 0;
    static cudaStream_t s1;
    static cudaEvent_t evFork, evPre;
    if (!inited) {
        cudaFuncSetAttribute(gemm_kernel, cudaFuncAttributeMaxDynamicSharedMemorySize, GEMM_SMEM);
        cudaStreamCreateWithFlags(&s1, cudaStreamNonBlocking);
        cudaEventCreateWithFlags(&evFork, cudaEventDisableTiming);
        cudaEventCreateWithFlags(&evPre, cudaEventDisableTiming);
        inited = 1;
    }

    const int nblk1 = (SEG + 511) / 512;   // 586

    // fork: precompute branch on s1 (independent of CSR build)
    cudaEventRecord(evFork, 0);
    cudaStreamWaitEvent(s1, evFork, 0);
    if (out_size >= NN * FF + RR * FF * FF) {
        cudaMemcpyAsync(out + (size_t)NN * FF, W,
                        sizeof(float) * RR * FF * FF, cudaMemcpyDeviceToDevice, s1);
    }
    precompute_kernel<<<RR * FF + FF, 128, 0, s1>>>(W, att1, att2, Wc);
    nodeh_convert_kernel<<<(NN * FF / 8 + 255) / 256, 256, 0, s1>>>(node_h);
    cudaEventRecord(evPre, s1);

    // CSR branch on stream 0 (g_cnt is all-zero: static init / restored by gemm)
    hist_kernel<<<(EE / 8 + 255) / 256, 256>>>((const int4*)edst, (const int4*)erel);
    scan1_kernel<<<nblk1, 512>>>();
    scan2_kernel<<<1, 1024>>>(nblk1);
    permute_kernel<<<(EE / 4 + 255) / 256, 256>>>((const int4*)esrc, (const int4*)edst,
                                                  (const int4*)erel);

    // join precompute before gather
    cudaStreamWaitEvent(0, evPre, 0);

    gather_kernel<<<(SEG + 7) / 8, 256>>>();
    gemm_kernel<<<(NN + 63) / 64, 256, GEMM_SMEM>>>(out, bc);
}